// round 1
// baseline (speedup 1.0000x reference)
#include <cuda_runtime.h>

#define BB 8
#define SS 1024
#define DD 1024
#define HH 8
#define DH 128
#define NTOK (BB*SS)      // 8192
#define SCALE 0.08838834764831845f   // 1/sqrt(128)

// Scratch (device globals: no allocations allowed)
__device__ float g_k[BB*HH*SS*DH];   // [b][h][s][d]
__device__ float g_q[BB*HH*DH*SS];   // [b][h][d][s]  (transposed for coalesced attn loads)
__device__ float g_v[BB*HH*SS*DH];   // [b][h][s][d]

// ---------------------------------------------------------------------------
// Kernel A: fused projection GEMM  C[m][n] = A[m][:] . W[n][:] + bias[n]
//   n in [0,1024)    -> k  (v_w, v_b)
//   n in [1024,3072) -> q/v (c_w, c_b rows n-1024)
// Tile 128m x 64n, K-slab 8, 256 threads, 8x4 register tile.
// ---------------------------------------------------------------------------
__global__ __launch_bounds__(256) void proj_kernel(
    const float* __restrict__ A,
    const float* __restrict__ c_w, const float* __restrict__ c_b,
    const float* __restrict__ v_w, const float* __restrict__ v_b)
{
    __shared__ float As[8][128];
    __shared__ float Bs[8][68];

    const int m0 = blockIdx.y * 128;
    const int n0 = blockIdx.x * 64;

    const float* Wp; const float* bp;
    if (n0 < DD) { Wp = v_w + (size_t)n0 * DD; bp = v_b + n0; }
    else         { Wp = c_w + (size_t)(n0 - DD) * DD; bp = c_b + (n0 - DD); }

    const int tid = threadIdx.x;
    const int tx = tid & 15;     // n-group: n = tx*4
    const int ty = tid >> 4;     // m-group: m = ty*8

    const int la_m = tid >> 1;           // 0..127
    const int la_k = (tid & 1) * 4;      // 0 or 4
    const int lb_n = tid >> 2;           // 0..63
    const int lb_k = (tid & 3) * 2;      // 0,2,4,6

    float acc[8][4];
#pragma unroll
    for (int i = 0; i < 8; i++)
#pragma unroll
        for (int j = 0; j < 4; j++) acc[i][j] = 0.f;

    for (int k0 = 0; k0 < DD; k0 += 8) {
        float4 av = *(const float4*)&A[(size_t)(m0 + la_m) * DD + k0 + la_k];
        float2 bv = *(const float2*)&Wp[(size_t)lb_n * DD + k0 + lb_k];
        __syncthreads();
        As[la_k + 0][la_m] = av.x;
        As[la_k + 1][la_m] = av.y;
        As[la_k + 2][la_m] = av.z;
        As[la_k + 3][la_m] = av.w;
        Bs[lb_k + 0][lb_n] = bv.x;
        Bs[lb_k + 1][lb_n] = bv.y;
        __syncthreads();
#pragma unroll
        for (int kk = 0; kk < 8; kk++) {
            float a[8], b[4];
            *(float4*)&a[0] = *(const float4*)&As[kk][ty * 8];
            *(float4*)&a[4] = *(const float4*)&As[kk][ty * 8 + 4];
            *(float4*)&b[0] = *(const float4*)&Bs[kk][tx * 4];
#pragma unroll
            for (int i = 0; i < 8; i++)
#pragma unroll
                for (int j = 0; j < 4; j++) acc[i][j] += a[i] * b[j];
        }
    }

    const int n_base = n0 + tx * 4;
    const int kind = n_base >> 10;          // 0=k,1=q,2=v
    const int h = (n_base >> 7) & 7;
    const int d = n_base & 127;
    float bias[4];
#pragma unroll
    for (int j = 0; j < 4; j++) bias[j] = bp[tx * 4 + j];

#pragma unroll
    for (int i = 0; i < 8; i++) {
        int m = m0 + ty * 8 + i;
        int b_ = m >> 10, s = m & 1023;
        float4 r;
        r.x = acc[i][0] + bias[0];
        r.y = acc[i][1] + bias[1];
        r.z = acc[i][2] + bias[2];
        r.w = acc[i][3] + bias[3];
        if (kind == 1) {
            size_t base = ((size_t)(b_ * HH + h) * DH + d) * SS + s;
            g_q[base]          = r.x;
            g_q[base + SS]     = r.y;
            g_q[base + 2*SS]   = r.z;
            g_q[base + 3*SS]   = r.w;
        } else {
            float* dst = (kind == 0) ? g_k : g_v;
            size_t off = ((size_t)(b_ * HH + h) * SS + s) * DH + d;
            *(float4*)&dst[off] = r;
        }
    }
}

// ---------------------------------------------------------------------------
// Kernel B: attention for a 32-row i-tile of one (b,h).
//  - scores panel kept j-major in SMEM: sSt[1024][36] (i-cols padded)
//  - softmax (1 pass, exp left unnormalized; R scaled by 1/sum at the end)
//  - writes w and updated_m
// ---------------------------------------------------------------------------
#define TI 32
#define PADI 36
#define TJQ 64
#define TJV 64
#define SMEM_FLOATS (SS*PADI + DH*PADI + 8704 + 1024 + 32)

__global__ __launch_bounds__(256) void attn_kernel(
    const float* __restrict__ m_feats,
    const int*   __restrict__ mask,
    float* __restrict__ out)
{
    extern __shared__ float sm[];
    float* sSt  = sm;                       // [1024][PADI]
    float* sKt  = sSt + SS * PADI;          // [128][PADI]
    float* sQV  = sKt + DH * PADI;          // Q: [128][68] / V: [64][132] (union, 8704 floats)
    int*   sMask = (int*)(sQV + 8704);      // [1024]
    float* sInv  = (float*)(sMask + 1024);  // [32]

    const int tid = threadIdx.x;
    const int b  = blockIdx.z;
    const int h  = blockIdx.y;
    const int i0 = blockIdx.x * TI;

    const float* gK = g_k + (size_t)(b * HH + h) * SS * DH;
    const float* gQ = g_q + (size_t)(b * HH + h) * DH * SS;
    const float* gV = g_v + (size_t)(b * HH + h) * SS * DH;

    // Load K tile transposed: sKt[d][i]
    for (int p = tid; p < TI * DH / 4; p += 256) {
        int i = p & 31;
        int d = (p >> 5) * 4;
        float4 v = *(const float4*)&gK[(size_t)(i0 + i) * DH + d];
        sKt[(d + 0) * PADI + i] = v.x;
        sKt[(d + 1) * PADI + i] = v.y;
        sKt[(d + 2) * PADI + i] = v.z;
        sKt[(d + 3) * PADI + i] = v.w;
    }
    for (int j = tid; j < SS; j += 256) sMask[j] = mask[b * SS + j];
    __syncthreads();

    const int tx = tid & 31;   // scores: j = 2*tx ; PV: d = 4*tx
    const int ty = tid >> 5;   // i = 4*ty

    // ---------------- Phase 1: scores ----------------
    for (int jt = 0; jt < SS; jt += TJQ) {
        // load Q tile d-major: sQV[d*68 + j], coalesced (g_q is [d][s])
        for (int p = tid; p < DH * TJQ / 4; p += 256) {
            int d = p >> 4;
            int j4 = (p & 15) * 4;
            float4 v = *(const float4*)&gQ[(size_t)d * SS + jt + j4];
            *(float4*)&sQV[d * 68 + j4] = v;
        }
        __syncthreads();

        float acc[4][2];
#pragma unroll
        for (int i = 0; i < 4; i++) { acc[i][0] = 0.f; acc[i][1] = 0.f; }
#pragma unroll 8
        for (int d = 0; d < DH; d++) {
            float4 a  = *(const float4*)&sKt[d * PADI + ty * 4];
            float2 bq = *(const float2*)&sQV[d * 68 + tx * 2];
            acc[0][0] += a.x * bq.x;  acc[0][1] += a.x * bq.y;
            acc[1][0] += a.y * bq.x;  acc[1][1] += a.y * bq.y;
            acc[2][0] += a.z * bq.x;  acc[2][1] += a.z * bq.y;
            acc[3][0] += a.w * bq.x;  acc[3][1] += a.w * bq.y;
        }
#pragma unroll
        for (int c = 0; c < 2; c++) {
            int jg = jt + tx * 2 + c;
            bool m = (sMask[jg] != 0);
            float4 r;
            r.x = m ? acc[0][c] * SCALE : -1e9f;
            r.y = m ? acc[1][c] * SCALE : -1e9f;
            r.z = m ? acc[2][c] * SCALE : -1e9f;
            r.w = m ? acc[3][c] * SCALE : -1e9f;
            *(float4*)&sSt[(size_t)jg * PADI + ty * 4] = r;
        }
        __syncthreads();
    }

    // ---------------- Phase 2: softmax + write w ----------------
    {
        const int warp = tid >> 5, lane = tid & 31;
        for (int r = 0; r < 4; r++) {
            int i = warp * 4 + r;
            float mx = -3.0e38f;
            for (int j = lane; j < SS; j += 32)
                mx = fmaxf(mx, sSt[(size_t)j * PADI + i]);
#pragma unroll
            for (int o = 16; o; o >>= 1) mx = fmaxf(mx, __shfl_xor_sync(~0u, mx, o));
            float sum = 0.f;
            for (int j = lane; j < SS; j += 32) {
                float e = __expf(sSt[(size_t)j * PADI + i] - mx);
                sSt[(size_t)j * PADI + i] = e;
                sum += e;
            }
#pragma unroll
            for (int o = 16; o; o >>= 1) sum += __shfl_xor_sync(~0u, sum, o);
            float inv = 1.0f / sum;
            if (lane == 0) sInv[i] = inv;
            float* wout = out + (size_t)BB * SS * DD
                        + (((size_t)(b * HH + h)) * SS + (i0 + i)) * SS;
            for (int j = lane; j < SS; j += 32)
                wout[j] = sSt[(size_t)j * PADI + i] * inv;
        }
    }
    __syncthreads();

    // ---------------- Phase 3: R = P @ V ----------------
    float racc[4][4];
#pragma unroll
    for (int i = 0; i < 4; i++)
#pragma unroll
        for (int j = 0; j < 4; j++) racc[i][j] = 0.f;

    for (int jt = 0; jt < SS; jt += TJV) {
        for (int p = tid; p < TJV * DH / 4; p += 256) {
            int j = p >> 5;
            int d4 = (p & 31) * 4;
            float4 v = *(const float4*)&gV[(size_t)(jt + j) * DH + d4];
            *(float4*)&sQV[j * 132 + d4] = v;
        }
        __syncthreads();
#pragma unroll 4
        for (int j = 0; j < TJV; j++) {
            float4 w4 = *(const float4*)&sSt[(size_t)(jt + j) * PADI + ty * 4];
            float4 v4 = *(const float4*)&sQV[j * 132 + tx * 4];
            racc[0][0] += w4.x * v4.x; racc[0][1] += w4.x * v4.y;
            racc[0][2] += w4.x * v4.z; racc[0][3] += w4.x * v4.w;
            racc[1][0] += w4.y * v4.x; racc[1][1] += w4.y * v4.y;
            racc[1][2] += w4.y * v4.z; racc[1][3] += w4.y * v4.w;
            racc[2][0] += w4.z * v4.x; racc[2][1] += w4.z * v4.y;
            racc[2][2] += w4.z * v4.z; racc[2][3] += w4.z * v4.w;
            racc[3][0] += w4.w * v4.x; racc[3][1] += w4.w * v4.y;
            racc[3][2] += w4.w * v4.z; racc[3][3] += w4.w * v4.w;
        }
        __syncthreads();
    }

    // ---------------- Epilogue: updated_m = m_feats + R/sum ----------------
#pragma unroll
    for (int ii = 0; ii < 4; ii++) {
        int i = ty * 4 + ii;
        float inv = sInv[i];
        size_t off = ((size_t)b * SS + i0 + i) * DD + h * DH + tx * 4;
        float4 mf = *(const float4*)&m_feats[off];
        float4 r;
        r.x = mf.x + racc[ii][0] * inv;
        r.y = mf.y + racc[ii][1] * inv;
        r.z = mf.z + racc[ii][2] * inv;
        r.w = mf.w + racc[ii][3] * inv;
        *(float4*)&out[off] = r;
    }
}

extern "C" void kernel_launch(void* const* d_in, const int* in_sizes, int n_in,
                              void* d_out, int out_size)
{
    const float* m_feats = (const float*)d_in[0];
    const int*   mask    = (const int*)d_in[1];
    const float* c_w     = (const float*)d_in[2];
    const float* c_b     = (const float*)d_in[3];
    const float* v_w     = (const float*)d_in[4];
    const float* v_b     = (const float*)d_in[5];
    float* out = (float*)d_out;

    dim3 gA(48, 64);     // 3072/64 n-tiles, 8192/128 m-tiles
    proj_kernel<<<gA, 256>>>(m_feats, c_w, c_b, v_w, v_b);

    const size_t smemB = (size_t)SMEM_FLOATS * sizeof(float);  // 204,928 B
    cudaFuncSetAttribute(attn_kernel,
                         cudaFuncAttributeMaxDynamicSharedMemorySize, (int)smemB);
    dim3 gB(SS / TI, HH, BB);   // (32, 8, 8)
    attn_kernel<<<gB, 256, smemB>>>(m_feats, mask, out);
}

// round 4
// speedup vs baseline: 1.3237x; 1.3237x over previous
#include <cuda_runtime.h>
#include <cuda_bf16.h>
#include <cstdint>

#define BB 8
#define SS 1024
#define DD 1024
#define HH 8
#define DH 128
#define NN 3072                      // 1024 k + 1024 q + 1024 v output cols
#define SCALE 0.08838834764831845f   // 1/sqrt(128)

// ---------------------------------------------------------------------------
// Device scratch (no allocations allowed)
// ---------------------------------------------------------------------------
__device__ float g_k[BB*HH*SS*DH];            // [b][h][s][d]
__device__ float g_q[BB*HH*DH*SS];            // [b][h][d][s]  (transposed)
__device__ float g_v[BB*HH*SS*DH];            // [b][h][s][d]
__device__ __nv_bfloat16 g_Ah[BB*SS*DD];      // m_feats hi
__device__ __nv_bfloat16 g_Al[BB*SS*DD];      // m_feats lo
__device__ __nv_bfloat16 g_Wh[NN*DD];         // [v_w ; c_w] hi
__device__ __nv_bfloat16 g_Wl[NN*DD];         // lo

// ---------------------------------------------------------------------------
// Split-precision conversion
// ---------------------------------------------------------------------------
__device__ __forceinline__ void split4(float4 v, __nv_bfloat162* hi2, __nv_bfloat162* lo2) {
    __nv_bfloat16 hx = __float2bfloat16_rn(v.x);
    __nv_bfloat16 hy = __float2bfloat16_rn(v.y);
    __nv_bfloat16 hz = __float2bfloat16_rn(v.z);
    __nv_bfloat16 hw = __float2bfloat16_rn(v.w);
    hi2[0] = __nv_bfloat162(hx, hy);
    hi2[1] = __nv_bfloat162(hz, hw);
    lo2[0] = __nv_bfloat162(__float2bfloat16_rn(v.x - __bfloat162float(hx)),
                            __float2bfloat16_rn(v.y - __bfloat162float(hy)));
    lo2[1] = __nv_bfloat162(__float2bfloat16_rn(v.z - __bfloat162float(hz)),
                            __float2bfloat16_rn(v.w - __bfloat162float(hw)));
}

__global__ __launch_bounds__(256) void convA_kernel(const float* __restrict__ A) {
    int i4 = blockIdx.x * 256 + threadIdx.x;
    if (i4 >= BB*SS*DD/4) return;
    float4 v = ((const float4*)A)[i4];
    __nv_bfloat162 h[2], l[2];
    split4(v, h, l);
    ((__nv_bfloat162*)g_Ah)[i4*2]   = h[0];
    ((__nv_bfloat162*)g_Ah)[i4*2+1] = h[1];
    ((__nv_bfloat162*)g_Al)[i4*2]   = l[0];
    ((__nv_bfloat162*)g_Al)[i4*2+1] = l[1];
}

__global__ __launch_bounds__(256) void convW_kernel(const float* __restrict__ c_w,
                                                    const float* __restrict__ v_w) {
    int i4 = blockIdx.x * 256 + threadIdx.x;
    if (i4 >= NN*DD/4) return;
    int e = i4 * 4;
    int n = e >> 10, k = e & 1023;
    const float* src = (n < DD) ? (v_w + (size_t)n * DD + k)
                                : (c_w + (size_t)(n - DD) * DD + k);
    float4 v = *(const float4*)src;
    __nv_bfloat162 h[2], l[2];
    split4(v, h, l);
    ((__nv_bfloat162*)g_Wh)[i4*2]   = h[0];
    ((__nv_bfloat162*)g_Wh)[i4*2+1] = h[1];
    ((__nv_bfloat162*)g_Wl)[i4*2]   = l[0];
    ((__nv_bfloat162*)g_Wl)[i4*2+1] = l[1];
}

// ---------------------------------------------------------------------------
// mma.sync helpers (plain sm_103-target-safe)
// ---------------------------------------------------------------------------
__device__ __forceinline__ uint32_t smem_u32(const void* p) {
    uint32_t a;
    asm("{ .reg .u64 t; cvta.to.shared.u64 t, %1; cvt.u32.u64 %0, t; }" : "=r"(a) : "l"(p));
    return a;
}

__device__ __forceinline__ void ldsm_x4(uint32_t* r, uint32_t addr) {
    asm volatile("ldmatrix.sync.aligned.m8n8.x4.shared.b16 {%0,%1,%2,%3}, [%4];"
                 : "=r"(r[0]), "=r"(r[1]), "=r"(r[2]), "=r"(r[3]) : "r"(addr));
}

__device__ __forceinline__ void mma_bf16(float* c, const uint32_t* a, uint32_t b0, uint32_t b1) {
    asm volatile(
        "mma.sync.aligned.m16n8k16.row.col.f32.bf16.bf16.f32 "
        "{%0,%1,%2,%3}, {%4,%5,%6,%7}, {%8,%9}, {%0,%1,%2,%3};"
        : "+f"(c[0]), "+f"(c[1]), "+f"(c[2]), "+f"(c[3])
        : "r"(a[0]), "r"(a[1]), "r"(a[2]), "r"(a[3]), "r"(b0), "r"(b1));
}

// ---------------------------------------------------------------------------
// Projection GEMM: C[8192,3072] = A @ W^T + bias  (split-bf16, 3 MMA passes)
// CTA 128x128, 8 warps (4m x 2n), warp tile 32x64, K-chunk 32, double buffer.
// SMEM rows padded to 40 bf16 (80B) -> conflict-free ldmatrix.
// ---------------------------------------------------------------------------
#define KC 32
#define ROWP 40
#define BUF_E (128*ROWP)                 // bf16 elems per operand per buffer
#define OFF_AH 0
#define OFF_AL (2*BUF_E)
#define OFF_BH (4*BUF_E)
#define OFF_BL (6*BUF_E)
#define GEMM_SMEM_B (8*BUF_E*2 + 512)    // 81920 bytes data + 512 bias

__device__ __forceinline__ void g2r(uint4* r, const __nv_bfloat16* g, int tid, int k0) {
#pragma unroll
    for (int j = 0; j < 2; j++) {
        int u = tid + j * 256;           // 0..511
        int row = u >> 2, seg = u & 3;
        r[j] = *(const uint4*)(g + (size_t)row * DD + k0 + seg * 8);
    }
}
__device__ __forceinline__ void r2s(__nv_bfloat16* s, const uint4* r, int tid) {
#pragma unroll
    for (int j = 0; j < 2; j++) {
        int u = tid + j * 256;
        int row = u >> 2, seg = u & 3;
        *(uint4*)(s + row * ROWP + seg * 8) = r[j];
    }
}

__global__ __launch_bounds__(256, 1) void gemm_kernel(const float* __restrict__ c_b,
                                                      const float* __restrict__ v_b) {
    extern __shared__ __nv_bfloat16 sm[];
    float* sBias = (float*)(sm + 8 * BUF_E);   // byte offset 81920 (FIXED)

    const int tid  = threadIdx.x;
    const int lane = tid & 31;
    const int wid  = tid >> 5;
    const int wm   = wid >> 1;          // 0..3 -> m offset wm*32
    const int wn   = wid & 1;           // 0..1 -> n offset wn*64
    const int n0   = blockIdx.x * 128;
    const int m0   = blockIdx.y * 128;

    const __nv_bfloat16* Ah = g_Ah + (size_t)m0 * DD;
    const __nv_bfloat16* Al = g_Al + (size_t)m0 * DD;
    const __nv_bfloat16* Bh = g_Wh + (size_t)n0 * DD;
    const __nv_bfloat16* Bl = g_Wl + (size_t)n0 * DD;

    const float* bp = (n0 < DD) ? (v_b + n0) : (c_b + (n0 - DD));
    if (tid < 128) sBias[tid] = bp[tid];

    float acc[2][8][4];
#pragma unroll
    for (int i = 0; i < 2; i++)
#pragma unroll
        for (int j = 0; j < 8; j++)
#pragma unroll
            for (int c = 0; c < 4; c++) acc[i][j][c] = 0.f;

    const int lrow_a = wm * 32 + (lane & 15);
    const int lrow_b0 = wn * 64 + (lane & 15);
    const int lk = ((lane >> 4) & 1) * 8;

    // prologue: chunk 0
    {
        uint4 rah[2], ral[2], rbh[2], rbl[2];
        g2r(rah, Ah, tid, 0); g2r(ral, Al, tid, 0);
        g2r(rbh, Bh, tid, 0); g2r(rbl, Bl, tid, 0);
        r2s(sm + OFF_AH, rah, tid); r2s(sm + OFF_AL, ral, tid);
        r2s(sm + OFF_BH, rbh, tid); r2s(sm + OFF_BL, rbl, tid);
    }
    __syncthreads();

#pragma unroll 1
    for (int c = 0; c < DD / KC; c++) {
        const int cur = c & 1;
        uint4 rah[2], ral[2], rbh[2], rbl[2];
        if (c + 1 < DD / KC) {
            int k0 = (c + 1) * KC;
            g2r(rah, Ah, tid, k0); g2r(ral, Al, tid, k0);
            g2r(rbh, Bh, tid, k0); g2r(rbl, Bl, tid, k0);
        }

        const __nv_bfloat16* base = sm + cur * BUF_E;
#pragma unroll
        for (int kk = 0; kk < 2; kk++) {
            const int ke = kk * 16 + lk;
            uint32_t ah[2][4], al[2][4], bh[4][4], bl[4][4];
#pragma unroll
            for (int mi = 0; mi < 2; mi++) {
                uint32_t ad = smem_u32(base + OFF_AH + (lrow_a + mi * 16) * ROWP + ke);
                ldsm_x4(ah[mi], ad);
                ldsm_x4(al[mi], ad + (OFF_AL - OFF_AH) * 2);
            }
#pragma unroll
            for (int nb = 0; nb < 4; nb++) {
                uint32_t bd = smem_u32(base + OFF_BH + (lrow_b0 + nb * 16) * ROWP + ke);
                ldsm_x4(bh[nb], bd);
                ldsm_x4(bl[nb], bd + (OFF_BL - OFF_BH) * 2);
            }
#pragma unroll
            for (int mi = 0; mi < 2; mi++)
#pragma unroll
                for (int nb = 0; nb < 4; nb++) {
                    mma_bf16(acc[mi][nb*2+0], ah[mi], bh[nb][0], bh[nb][2]);
                    mma_bf16(acc[mi][nb*2+1], ah[mi], bh[nb][1], bh[nb][3]);
                    mma_bf16(acc[mi][nb*2+0], ah[mi], bl[nb][0], bl[nb][2]);
                    mma_bf16(acc[mi][nb*2+1], ah[mi], bl[nb][1], bl[nb][3]);
                    mma_bf16(acc[mi][nb*2+0], al[mi], bh[nb][0], bh[nb][2]);
                    mma_bf16(acc[mi][nb*2+1], al[mi], bh[nb][1], bh[nb][3]);
                }
        }

        if (c + 1 < DD / KC) {
            __nv_bfloat16* nb_ = sm + (cur ^ 1) * BUF_E;
            r2s(nb_ + OFF_AH, rah, tid); r2s(nb_ + OFF_AL, ral, tid);
            r2s(nb_ + OFF_BH, rbh, tid); r2s(nb_ + OFF_BL, rbl, tid);
        }
        __syncthreads();
    }

    // ---------------- epilogue ----------------
    const int kind = n0 >> 10;          // 0=k, 1=q, 2=v
    const int h = (n0 >> 7) & 7;
    const int b_ = m0 >> 10;
    const int g = lane >> 2;            // row within m8 group
    const int tc = (lane & 3) * 2;      // col pair

#pragma unroll
    for (int mi = 0; mi < 2; mi++) {
#pragma unroll
        for (int nj = 0; nj < 8; nj++) {
            const float* a4 = acc[mi][nj];
            int d = wn * 64 + nj * 8 + tc;
            float bx = sBias[d], by = sBias[d + 1];
            int mrow = m0 + wm * 32 + mi * 16 + g;
            int s0 = mrow & 1023;
            if (kind == 1) {
                float* dq = g_q + ((size_t)(b_ * HH + h) * DH + d) * SS;
                dq[s0]          = a4[0] + bx;
                dq[SS + s0]     = a4[1] + by;
                dq[s0 + 8]      = a4[2] + bx;
                dq[SS + s0 + 8] = a4[3] + by;
            } else {
                float* dst = ((kind == 0) ? g_k : g_v) + (size_t)(b_ * HH + h) * SS * DH;
                float2 r0 = make_float2(a4[0] + bx, a4[1] + by);
                float2 r1 = make_float2(a4[2] + bx, a4[3] + by);
                *(float2*)(dst + (size_t)s0 * DH + d)       = r0;
                *(float2*)(dst + (size_t)(s0 + 8) * DH + d) = r1;
            }
        }
    }
}

// ---------------------------------------------------------------------------
// Attention kernel (unchanged)
// ---------------------------------------------------------------------------
#define TI 32
#define PADI 36
#define TJQ 64
#define TJV 64
#define SMEM_FLOATS (SS*PADI + DH*PADI + 8704 + 1024 + 32)

__global__ __launch_bounds__(256) void attn_kernel(
    const float* __restrict__ m_feats,
    const int*   __restrict__ mask,
    float* __restrict__ out)
{
    extern __shared__ float smf[];
    float* sSt  = smf;
    float* sKt  = sSt + SS * PADI;
    float* sQV  = sKt + DH * PADI;
    int*   sMask = (int*)(sQV + 8704);
    float* sInv  = (float*)(sMask + 1024);

    const int tid = threadIdx.x;
    const int b  = blockIdx.z;
    const int h  = blockIdx.y;
    const int i0 = blockIdx.x * TI;

    const float* gK = g_k + (size_t)(b * HH + h) * SS * DH;
    const float* gQ = g_q + (size_t)(b * HH + h) * DH * SS;
    const float* gV = g_v + (size_t)(b * HH + h) * SS * DH;

    for (int p = tid; p < TI * DH / 4; p += 256) {
        int i = p & 31;
        int d = (p >> 5) * 4;
        float4 v = *(const float4*)&gK[(size_t)(i0 + i) * DH + d];
        sKt[(d + 0) * PADI + i] = v.x;
        sKt[(d + 1) * PADI + i] = v.y;
        sKt[(d + 2) * PADI + i] = v.z;
        sKt[(d + 3) * PADI + i] = v.w;
    }
    for (int j = tid; j < SS; j += 256) sMask[j] = mask[b * SS + j];
    __syncthreads();

    const int tx = tid & 31;
    const int ty = tid >> 5;

    for (int jt = 0; jt < SS; jt += TJQ) {
        for (int p = tid; p < DH * TJQ / 4; p += 256) {
            int d = p >> 4;
            int j4 = (p & 15) * 4;
            float4 v = *(const float4*)&gQ[(size_t)d * SS + jt + j4];
            *(float4*)&sQV[d * 68 + j4] = v;
        }
        __syncthreads();

        float acc[4][2];
#pragma unroll
        for (int i = 0; i < 4; i++) { acc[i][0] = 0.f; acc[i][1] = 0.f; }
#pragma unroll 8
        for (int d = 0; d < DH; d++) {
            float4 a  = *(const float4*)&sKt[d * PADI + ty * 4];
            float2 bq = *(const float2*)&sQV[d * 68 + tx * 2];
            acc[0][0] += a.x * bq.x;  acc[0][1] += a.x * bq.y;
            acc[1][0] += a.y * bq.x;  acc[1][1] += a.y * bq.y;
            acc[2][0] += a.z * bq.x;  acc[2][1] += a.z * bq.y;
            acc[3][0] += a.w * bq.x;  acc[3][1] += a.w * bq.y;
        }
#pragma unroll
        for (int c = 0; c < 2; c++) {
            int jg = jt + tx * 2 + c;
            bool m = (sMask[jg] != 0);
            float4 r;
            r.x = m ? acc[0][c] * SCALE : -1e9f;
            r.y = m ? acc[1][c] * SCALE : -1e9f;
            r.z = m ? acc[2][c] * SCALE : -1e9f;
            r.w = m ? acc[3][c] * SCALE : -1e9f;
            *(float4*)&sSt[(size_t)jg * PADI + ty * 4] = r;
        }
        __syncthreads();
    }

    {
        const int warp = tid >> 5, lane = tid & 31;
        for (int r = 0; r < 4; r++) {
            int i = warp * 4 + r;
            float mx = -3.0e38f;
            for (int j = lane; j < SS; j += 32)
                mx = fmaxf(mx, sSt[(size_t)j * PADI + i]);
#pragma unroll
            for (int o = 16; o; o >>= 1) mx = fmaxf(mx, __shfl_xor_sync(~0u, mx, o));
            float sum = 0.f;
            for (int j = lane; j < SS; j += 32) {
                float e = __expf(sSt[(size_t)j * PADI + i] - mx);
                sSt[(size_t)j * PADI + i] = e;
                sum += e;
            }
#pragma unroll
            for (int o = 16; o; o >>= 1) sum += __shfl_xor_sync(~0u, sum, o);
            float inv = 1.0f / sum;
            if (lane == 0) sInv[i] = inv;
            float* wout = out + (size_t)BB * SS * DD
                        + (((size_t)(b * HH + h)) * SS + (i0 + i)) * SS;
            for (int j = lane; j < SS; j += 32)
                wout[j] = sSt[(size_t)j * PADI + i] * inv;
        }
    }
    __syncthreads();

    float racc[4][4];
#pragma unroll
    for (int i = 0; i < 4; i++)
#pragma unroll
        for (int j = 0; j < 4; j++) racc[i][j] = 0.f;

    for (int jt = 0; jt < SS; jt += TJV) {
        for (int p = tid; p < TJV * DH / 4; p += 256) {
            int j = p >> 5;
            int d4 = (p & 31) * 4;
            float4 v = *(const float4*)&gV[(size_t)(jt + j) * DH + d4];
            *(float4*)&sQV[j * 132 + d4] = v;
        }
        __syncthreads();
#pragma unroll 4
        for (int j = 0; j < TJV; j++) {
            float4 w4 = *(const float4*)&sSt[(size_t)(jt + j) * PADI + ty * 4];
            float4 v4 = *(const float4*)&sQV[j * 132 + tx * 4];
            racc[0][0] += w4.x * v4.x; racc[0][1] += w4.x * v4.y;
            racc[0][2] += w4.x * v4.z; racc[0][3] += w4.x * v4.w;
            racc[1][0] += w4.y * v4.x; racc[1][1] += w4.y * v4.y;
            racc[1][2] += w4.y * v4.z; racc[1][3] += w4.y * v4.w;
            racc[2][0] += w4.z * v4.x; racc[2][1] += w4.z * v4.y;
            racc[2][2] += w4.z * v4.z; racc[2][3] += w4.z * v4.w;
            racc[3][0] += w4.w * v4.x; racc[3][1] += w4.w * v4.y;
            racc[3][2] += w4.w * v4.z; racc[3][3] += w4.w * v4.w;
        }
        __syncthreads();
    }

#pragma unroll
    for (int ii = 0; ii < 4; ii++) {
        int i = ty * 4 + ii;
        float inv = sInv[i];
        size_t off = ((size_t)b * SS + i0 + i) * DD + h * DH + tx * 4;
        float4 mf = *(const float4*)&m_feats[off];
        float4 r;
        r.x = mf.x + racc[ii][0] * inv;
        r.y = mf.y + racc[ii][1] * inv;
        r.z = mf.z + racc[ii][2] * inv;
        r.w = mf.w + racc[ii][3] * inv;
        *(float4*)&out[off] = r;
    }
}

// ---------------------------------------------------------------------------
extern "C" void kernel_launch(void* const* d_in, const int* in_sizes, int n_in,
                              void* d_out, int out_size)
{
    const float* m_feats = (const float*)d_in[0];
    const int*   mask    = (const int*)d_in[1];
    const float* c_w     = (const float*)d_in[2];
    const float* c_b     = (const float*)d_in[3];
    const float* v_w     = (const float*)d_in[4];
    const float* v_b     = (const float*)d_in[5];
    float* out = (float*)d_out;

    convA_kernel<<<BB*SS*DD/4/256, 256>>>(m_feats);
    convW_kernel<<<NN*DD/4/256, 256>>>(c_w, v_w);

    cudaFuncSetAttribute(gemm_kernel,
                         cudaFuncAttributeMaxDynamicSharedMemorySize, GEMM_SMEM_B);
    dim3 gG(NN / 128, BB * SS / 128);   // (24, 64)
    gemm_kernel<<<gG, 256, GEMM_SMEM_B>>>(c_b, v_b);

    const size_t smemB = (size_t)SMEM_FLOATS * sizeof(float);  // 204,928 B
    cudaFuncSetAttribute(attn_kernel,
                         cudaFuncAttributeMaxDynamicSharedMemorySize, (int)smemB);
    dim3 gB(SS / TI, HH, BB);
    attn_kernel<<<gB, 256, smemB>>>(m_feats, mask, out);
}

// round 5
// speedup vs baseline: 2.5761x; 1.9462x over previous
#include <cuda_runtime.h>
#include <cuda_bf16.h>
#include <cstdint>

#define BB 8
#define SS 1024
#define DD 1024
#define HH 8
#define DH 128
#define NN 3072
#define SCALE 0.08838834764831845f   // 1/sqrt(128)

// ---------------------------------------------------------------------------
// Device scratch
// ---------------------------------------------------------------------------
__device__ __nv_bfloat16 g_kh[BB*HH*SS*DH];   // K hi  [bh][s][d]
__device__ __nv_bfloat16 g_kl[BB*HH*SS*DH];   // K lo
__device__ __nv_bfloat16 g_qh[BB*HH*SS*DH];   // Q hi  [bh][s][d]
__device__ __nv_bfloat16 g_ql[BB*HH*SS*DH];   // Q lo
__device__ __nv_bfloat16 g_vth[BB*HH*DH*SS];  // V^T hi [bh][d][s]
__device__ __nv_bfloat16 g_Ah[BB*SS*DD];
__device__ __nv_bfloat16 g_Al[BB*SS*DD];
__device__ __nv_bfloat16 g_Wh[NN*DD];
__device__ __nv_bfloat16 g_Wl[NN*DD];

// ---------------------------------------------------------------------------
// Split conversion
// ---------------------------------------------------------------------------
__device__ __forceinline__ void split4(float4 v, __nv_bfloat162* hi2, __nv_bfloat162* lo2) {
    __nv_bfloat16 hx = __float2bfloat16_rn(v.x);
    __nv_bfloat16 hy = __float2bfloat16_rn(v.y);
    __nv_bfloat16 hz = __float2bfloat16_rn(v.z);
    __nv_bfloat16 hw = __float2bfloat16_rn(v.w);
    hi2[0] = __nv_bfloat162(hx, hy);
    hi2[1] = __nv_bfloat162(hz, hw);
    lo2[0] = __nv_bfloat162(__float2bfloat16_rn(v.x - __bfloat162float(hx)),
                            __float2bfloat16_rn(v.y - __bfloat162float(hy)));
    lo2[1] = __nv_bfloat162(__float2bfloat16_rn(v.z - __bfloat162float(hz)),
                            __float2bfloat16_rn(v.w - __bfloat162float(hw)));
}

__global__ __launch_bounds__(256) void convA_kernel(const float* __restrict__ A) {
    int i4 = blockIdx.x * 256 + threadIdx.x;
    if (i4 >= BB*SS*DD/4) return;
    float4 v = ((const float4*)A)[i4];
    __nv_bfloat162 h[2], l[2];
    split4(v, h, l);
    ((__nv_bfloat162*)g_Ah)[i4*2]   = h[0];
    ((__nv_bfloat162*)g_Ah)[i4*2+1] = h[1];
    ((__nv_bfloat162*)g_Al)[i4*2]   = l[0];
    ((__nv_bfloat162*)g_Al)[i4*2+1] = l[1];
}

__global__ __launch_bounds__(256) void convW_kernel(const float* __restrict__ c_w,
                                                    const float* __restrict__ v_w) {
    int i4 = blockIdx.x * 256 + threadIdx.x;
    if (i4 >= NN*DD/4) return;
    int e = i4 * 4;
    int n = e >> 10, k = e & 1023;
    const float* src = (n < DD) ? (v_w + (size_t)n * DD + k)
                                : (c_w + (size_t)(n - DD) * DD + k);
    float4 v = *(const float4*)src;
    __nv_bfloat162 h[2], l[2];
    split4(v, h, l);
    ((__nv_bfloat162*)g_Wh)[i4*2]   = h[0];
    ((__nv_bfloat162*)g_Wh)[i4*2+1] = h[1];
    ((__nv_bfloat162*)g_Wl)[i4*2]   = l[0];
    ((__nv_bfloat162*)g_Wl)[i4*2+1] = l[1];
}

// ---------------------------------------------------------------------------
// mma.sync helpers
// ---------------------------------------------------------------------------
__device__ __forceinline__ uint32_t smem_u32(const void* p) {
    uint32_t a;
    asm("{ .reg .u64 t; cvta.to.shared.u64 t, %1; cvt.u32.u64 %0, t; }" : "=r"(a) : "l"(p));
    return a;
}

__device__ __forceinline__ void ldsm_x4(uint32_t* r, uint32_t addr) {
    asm volatile("ldmatrix.sync.aligned.m8n8.x4.shared.b16 {%0,%1,%2,%3}, [%4];"
                 : "=r"(r[0]), "=r"(r[1]), "=r"(r[2]), "=r"(r[3]) : "r"(addr));
}

__device__ __forceinline__ void mma_bf16(float* c, const uint32_t* a, uint32_t b0, uint32_t b1) {
    asm volatile(
        "mma.sync.aligned.m16n8k16.row.col.f32.bf16.bf16.f32 "
        "{%0,%1,%2,%3}, {%4,%5,%6,%7}, {%8,%9}, {%0,%1,%2,%3};"
        : "+f"(c[0]), "+f"(c[1]), "+f"(c[2]), "+f"(c[3])
        : "r"(a[0]), "r"(a[1]), "r"(a[2]), "r"(a[3]), "r"(b0), "r"(b1));
}

__device__ __forceinline__ void store_hilo(__nv_bfloat16* bh_, __nv_bfloat16* bl_,
                                           size_t off, float x0, float x1) {
    __nv_bfloat16 h0 = __float2bfloat16_rn(x0), h1 = __float2bfloat16_rn(x1);
    *(__nv_bfloat162*)(bh_ + off) = __nv_bfloat162(h0, h1);
    *(__nv_bfloat162*)(bl_ + off) =
        __nv_bfloat162(__float2bfloat16_rn(x0 - __bfloat162float(h0)),
                       __float2bfloat16_rn(x1 - __bfloat162float(h1)));
}

// ---------------------------------------------------------------------------
// Projection GEMM (split-bf16 HMMA) -> bf16 K/Q (split) + V^T (hi)
// ---------------------------------------------------------------------------
#define KC 32
#define ROWP 40
#define BUF_E (128*ROWP)
#define OFF_AH 0
#define OFF_AL (2*BUF_E)
#define OFF_BH (4*BUF_E)
#define OFF_BL (6*BUF_E)
#define GEMM_SMEM_B (8*BUF_E*2 + 512)

__device__ __forceinline__ void g2r(uint4* r, const __nv_bfloat16* g, int tid, int k0) {
#pragma unroll
    for (int j = 0; j < 2; j++) {
        int u = tid + j * 256;
        int row = u >> 2, seg = u & 3;
        r[j] = *(const uint4*)(g + (size_t)row * DD + k0 + seg * 8);
    }
}
__device__ __forceinline__ void r2s(__nv_bfloat16* s, const uint4* r, int tid) {
#pragma unroll
    for (int j = 0; j < 2; j++) {
        int u = tid + j * 256;
        int row = u >> 2, seg = u & 3;
        *(uint4*)(s + row * ROWP + seg * 8) = r[j];
    }
}

__global__ __launch_bounds__(256, 1) void gemm_kernel(const float* __restrict__ c_b,
                                                      const float* __restrict__ v_b) {
    extern __shared__ __nv_bfloat16 sm[];
    float* sBias = (float*)(sm + 8 * BUF_E);

    const int tid  = threadIdx.x;
    const int lane = tid & 31;
    const int wid  = tid >> 5;
    const int wm   = wid >> 1;
    const int wn   = wid & 1;
    const int n0   = blockIdx.x * 128;
    const int m0   = blockIdx.y * 128;

    const __nv_bfloat16* Ah = g_Ah + (size_t)m0 * DD;
    const __nv_bfloat16* Al = g_Al + (size_t)m0 * DD;
    const __nv_bfloat16* Bh = g_Wh + (size_t)n0 * DD;
    const __nv_bfloat16* Bl = g_Wl + (size_t)n0 * DD;

    const float* bp = (n0 < DD) ? (v_b + n0) : (c_b + (n0 - DD));
    if (tid < 128) sBias[tid] = bp[tid];

    float acc[2][8][4];
#pragma unroll
    for (int i = 0; i < 2; i++)
#pragma unroll
        for (int j = 0; j < 8; j++)
#pragma unroll
            for (int c = 0; c < 4; c++) acc[i][j][c] = 0.f;

    const int lrow_a = wm * 32 + (lane & 15);
    const int lrow_b0 = wn * 64 + (lane & 15);
    const int lk = ((lane >> 4) & 1) * 8;

    {
        uint4 rah[2], ral[2], rbh[2], rbl[2];
        g2r(rah, Ah, tid, 0); g2r(ral, Al, tid, 0);
        g2r(rbh, Bh, tid, 0); g2r(rbl, Bl, tid, 0);
        r2s(sm + OFF_AH, rah, tid); r2s(sm + OFF_AL, ral, tid);
        r2s(sm + OFF_BH, rbh, tid); r2s(sm + OFF_BL, rbl, tid);
    }
    __syncthreads();

#pragma unroll 1
    for (int c = 0; c < DD / KC; c++) {
        const int cur = c & 1;
        uint4 rah[2], ral[2], rbh[2], rbl[2];
        if (c + 1 < DD / KC) {
            int k0 = (c + 1) * KC;
            g2r(rah, Ah, tid, k0); g2r(ral, Al, tid, k0);
            g2r(rbh, Bh, tid, k0); g2r(rbl, Bl, tid, k0);
        }

        const __nv_bfloat16* base = sm + cur * BUF_E;
#pragma unroll
        for (int kk = 0; kk < 2; kk++) {
            const int ke = kk * 16 + lk;
            uint32_t ah[2][4], al[2][4], bh[4][4], bl[4][4];
#pragma unroll
            for (int mi = 0; mi < 2; mi++) {
                uint32_t ad = smem_u32(base + OFF_AH + (lrow_a + mi * 16) * ROWP + ke);
                ldsm_x4(ah[mi], ad);
                ldsm_x4(al[mi], ad + (OFF_AL - OFF_AH) * 2);
            }
#pragma unroll
            for (int nb = 0; nb < 4; nb++) {
                uint32_t bd = smem_u32(base + OFF_BH + (lrow_b0 + nb * 16) * ROWP + ke);
                ldsm_x4(bh[nb], bd);
                ldsm_x4(bl[nb], bd + (OFF_BL - OFF_BH) * 2);
            }
#pragma unroll
            for (int mi = 0; mi < 2; mi++)
#pragma unroll
                for (int nb = 0; nb < 4; nb++) {
                    mma_bf16(acc[mi][nb*2+0], ah[mi], bh[nb][0], bh[nb][2]);
                    mma_bf16(acc[mi][nb*2+1], ah[mi], bh[nb][1], bh[nb][3]);
                    mma_bf16(acc[mi][nb*2+0], ah[mi], bl[nb][0], bl[nb][2]);
                    mma_bf16(acc[mi][nb*2+1], ah[mi], bl[nb][1], bl[nb][3]);
                    mma_bf16(acc[mi][nb*2+0], al[mi], bh[nb][0], bh[nb][2]);
                    mma_bf16(acc[mi][nb*2+1], al[mi], bh[nb][1], bh[nb][3]);
                }
        }

        if (c + 1 < DD / KC) {
            __nv_bfloat16* nb_ = sm + (cur ^ 1) * BUF_E;
            r2s(nb_ + OFF_AH, rah, tid); r2s(nb_ + OFF_AL, ral, tid);
            r2s(nb_ + OFF_BH, rbh, tid); r2s(nb_ + OFF_BL, rbl, tid);
        }
        __syncthreads();
    }

    // epilogue -> bf16 scratch
    const int kind = n0 >> 10;          // 0=k, 1=q, 2=v
    const int h = (n0 >> 7) & 7;
    const int b_ = m0 >> 10;
    const int g = lane >> 2;
    const int tc = (lane & 3) * 2;
    const size_t bh_off = (size_t)(b_ * HH + h);

#pragma unroll
    for (int mi = 0; mi < 2; mi++) {
#pragma unroll
        for (int nj = 0; nj < 8; nj++) {
            const float* a4 = acc[mi][nj];
            int d = wn * 64 + nj * 8 + tc;
            float bx = sBias[d], by = sBias[d + 1];
            int s0 = (m0 + wm * 32 + mi * 16 + g) & 1023;
            float x0 = a4[0] + bx, x1 = a4[1] + by;
            float x2 = a4[2] + bx, x3 = a4[3] + by;
            if (kind == 2) {
                __nv_bfloat16* dst = g_vth + bh_off * DH * SS;
                dst[(size_t)d * SS + s0]           = __float2bfloat16_rn(x0);
                dst[(size_t)(d + 1) * SS + s0]     = __float2bfloat16_rn(x1);
                dst[(size_t)d * SS + s0 + 8]       = __float2bfloat16_rn(x2);
                dst[(size_t)(d + 1) * SS + s0 + 8] = __float2bfloat16_rn(x3);
            } else {
                __nv_bfloat16* dh_ = (kind == 0) ? g_kh : g_qh;
                __nv_bfloat16* dl_ = (kind == 0) ? g_kl : g_ql;
                size_t base_off = (bh_off * SS + s0) * DH + d;
                store_hilo(dh_, dl_, base_off, x0, x1);
                store_hilo(dh_, dl_, base_off + 8 * DH, x2, x3);
            }
        }
    }
}

// ---------------------------------------------------------------------------
// Attention: HMMA scores (split K/Q) + fp32 softmax panel + HMMA P.V
// CTA: 32 i-rows x full j=1024 of one (b,h). 256 threads.
// ---------------------------------------------------------------------------
#define PP 1028                      // panel pitch (floats)
#define KP 136                       // K/Q tile pitch (bf16)
#define PHP 1032                     // Ph pitch (bf16)
#define VP 72                        // V tile pitch (bf16)

#define SOFF_S    0
#define SOFF_KH   131584
#define SOFF_KL   (SOFF_KH + 8704)
#define SOFF_QH   (SOFF_KH + 17408)
#define SOFF_QL   (SOFF_QH + 34816)
#define SOFF_PH   131584             // aliases K/Q region (phase 3)
#define SOFF_V    (SOFF_PH + 66048)
#define SOFF_MASK (SOFF_KH + 87040)  // 218624
#define SOFF_INV  (SOFF_MASK + 4096)
#define ATTN_SMEM (SOFF_INV + 256)   // 222976 bytes

__global__ __launch_bounds__(256, 1) void attn_kernel(
    const float* __restrict__ m_feats,
    const int*   __restrict__ mask,
    float* __restrict__ out)
{
    extern __shared__ char smc[];
    float*         sS    = (float*)(smc + SOFF_S);
    __nv_bfloat16* sKh   = (__nv_bfloat16*)(smc + SOFF_KH);
    __nv_bfloat16* sKl   = (__nv_bfloat16*)(smc + SOFF_KL);
    __nv_bfloat16* sQh   = (__nv_bfloat16*)(smc + SOFF_QH);
    __nv_bfloat16* sQl   = (__nv_bfloat16*)(smc + SOFF_QL);
    __nv_bfloat16* sPh   = (__nv_bfloat16*)(smc + SOFF_PH);
    __nv_bfloat16* sV    = (__nv_bfloat16*)(smc + SOFF_V);
    int*           sMask = (int*)(smc + SOFF_MASK);
    float*         sInv  = (float*)(smc + SOFF_INV);

    const int tid  = threadIdx.x;
    const int lane = tid & 31;
    const int wid  = tid >> 5;
    const int b  = blockIdx.z;
    const int h  = blockIdx.y;
    const int i0 = blockIdx.x * 32;
    const size_t bh = (size_t)(b * HH + h);

    // ---- load mask + K tile (hi/lo) ----
    for (int j = tid; j < SS; j += 256) sMask[j] = mask[b * SS + j];
#pragma unroll
    for (int it = 0; it < 2; it++) {
        int p = tid + it * 256;                 // 512 uint4 per matrix
        int row = p >> 4, seg = p & 15;
        size_t go = (bh * SS + i0 + row) * DH + seg * 8;
        *(uint4*)(sKh + row * KP + seg * 8) = *(const uint4*)(g_kh + go);
        *(uint4*)(sKl + row * KP + seg * 8) = *(const uint4*)(g_kl + go);
    }
    __syncthreads();

    const int wm = wid >> 2;        // 0..1
    const int wn = wid & 3;         // 0..3
    const int lr16 = lane & 15;
    const int lkb = (lane >> 4) * 8;
    const int grow = lane >> 2;
    const int gcol = (lane & 3) * 2;

    // ================= Phase 1: scores =================
#pragma unroll 1
    for (int ct = 0; ct < 8; ct++) {
        // load Q chunk (128 j x 128 d), hi/lo
#pragma unroll
        for (int it = 0; it < 8; it++) {
            int p = tid + it * 256;             // 2048 uint4 per matrix
            int row = p >> 4, seg = p & 15;
            size_t go = (bh * SS + ct * 128 + row) * DH + seg * 8;
            *(uint4*)(sQh + row * KP + seg * 8) = *(const uint4*)(g_qh + go);
            *(uint4*)(sQl + row * KP + seg * 8) = *(const uint4*)(g_ql + go);
        }
        __syncthreads();

        float acc[4][4];
#pragma unroll
        for (int i = 0; i < 4; i++)
#pragma unroll
            for (int j = 0; j < 4; j++) acc[i][j] = 0.f;

#pragma unroll
        for (int ks = 0; ks < 8; ks++) {
            const int ke = ks * 16 + lkb;
            uint32_t kh[4], kl[4], qh[2][4], ql[2][4];
            uint32_t ad = smem_u32(sKh + (wm * 16 + lr16) * KP + ke);
            ldsm_x4(kh, ad);
            ldsm_x4(kl, ad + (SOFF_KL - SOFF_KH));
#pragma unroll
            for (int nb = 0; nb < 2; nb++) {
                uint32_t bd = smem_u32(sQh + (wn * 32 + nb * 16 + lr16) * KP + ke);
                ldsm_x4(qh[nb], bd);
                ldsm_x4(ql[nb], bd + (SOFF_QL - SOFF_QH));
            }
#pragma unroll
            for (int nb = 0; nb < 2; nb++) {
                mma_bf16(acc[nb*2+0], kh, qh[nb][0], qh[nb][2]);
                mma_bf16(acc[nb*2+1], kh, qh[nb][1], qh[nb][3]);
                mma_bf16(acc[nb*2+0], kh, ql[nb][0], ql[nb][2]);
                mma_bf16(acc[nb*2+1], kh, ql[nb][1], ql[nb][3]);
                mma_bf16(acc[nb*2+0], kl, qh[nb][0], qh[nb][2]);
                mma_bf16(acc[nb*2+1], kl, qh[nb][1], qh[nb][3]);
            }
        }

        // write to fp32 panel with scale + mask
#pragma unroll
        for (int g8 = 0; g8 < 4; g8++) {
            int jg = ct * 128 + wn * 32 + g8 * 8 + gcol;
            bool m0 = sMask[jg] != 0, m1 = sMask[jg + 1] != 0;
            int ir = wm * 16 + grow;
            float2 r0, r1;
            r0.x = m0 ? acc[g8][0] * SCALE : -1e9f;
            r0.y = m1 ? acc[g8][1] * SCALE : -1e9f;
            r1.x = m0 ? acc[g8][2] * SCALE : -1e9f;
            r1.y = m1 ? acc[g8][3] * SCALE : -1e9f;
            *(float2*)&sS[ir * PP + jg]       = r0;
            *(float2*)&sS[(ir + 8) * PP + jg] = r1;
        }
        __syncthreads();
    }

    // ================= Phase 2: softmax + w + Ph pack =================
    {
        const size_t wbase = (size_t)BB * SS * DD + (bh * SS + i0) * SS;
#pragma unroll 1
        for (int r = 0; r < 4; r++) {
            int i = wid * 4 + r;
            float* rowp = sS + (size_t)i * PP;
            float mx = -3.0e38f;
            for (int j = lane; j < SS; j += 32) mx = fmaxf(mx, rowp[j]);
#pragma unroll
            for (int o = 16; o; o >>= 1) mx = fmaxf(mx, __shfl_xor_sync(~0u, mx, o));
            float sum = 0.f;
            __nv_bfloat16* prow = sPh + (size_t)i * PHP;
            for (int j = lane; j < SS; j += 32) {
                float e = __expf(rowp[j] - mx);
                rowp[j] = e;
                prow[j] = __float2bfloat16_rn(e);
                sum += e;
            }
#pragma unroll
            for (int o = 16; o; o >>= 1) sum += __shfl_xor_sync(~0u, sum, o);
            float inv = 1.0f / sum;
            if (lane == 0) sInv[i] = inv;
            float* wout = out + wbase + (size_t)i * SS;
            for (int j = lane; j < SS; j += 32) wout[j] = rowp[j] * inv;
        }
    }
    __syncthreads();

    // ================= Phase 3: R = P @ V^T-tiles =================
    float racc[4][4];
#pragma unroll
    for (int i = 0; i < 4; i++)
#pragma unroll
        for (int j = 0; j < 4; j++) racc[i][j] = 0.f;

#pragma unroll 1
    for (int jc = 0; jc < 16; jc++) {
        // load V chunk: 128 d-rows x 64 j-cols
#pragma unroll
        for (int it = 0; it < 4; it++) {
            int p = tid + it * 256;             // 1024 uint4
            int row = p >> 3, seg = p & 7;
            *(uint4*)(sV + row * VP + seg * 8) =
                *(const uint4*)(g_vth + (bh * DH + row) * SS + jc * 64 + seg * 8);
        }
        __syncthreads();

#pragma unroll
        for (int ks = 0; ks < 4; ks++) {
            uint32_t pa[4], vh[2][4];
            ldsm_x4(pa, smem_u32(sPh + (size_t)(wm * 16 + lr16) * PHP
                                 + jc * 64 + ks * 16 + lkb));
#pragma unroll
            for (int nb = 0; nb < 2; nb++)
                ldsm_x4(vh[nb], smem_u32(sV + (wn * 32 + nb * 16 + lr16) * VP
                                         + ks * 16 + lkb));
#pragma unroll
            for (int nb = 0; nb < 2; nb++) {
                mma_bf16(racc[nb*2+0], pa, vh[nb][0], vh[nb][2]);
                mma_bf16(racc[nb*2+1], pa, vh[nb][1], vh[nb][3]);
            }
        }
        __syncthreads();
    }

    // ---- epilogue: out = m_feats + R * inv ----
#pragma unroll
    for (int g8 = 0; g8 < 4; g8++) {
        int d = wn * 32 + g8 * 8 + gcol;
        int ir = wm * 16 + grow;
        float inv0 = sInv[ir], inv1 = sInv[ir + 8];
        size_t o0 = ((size_t)b * SS + i0 + ir) * DD + h * DH + d;
        float2 mf0 = *(const float2*)&m_feats[o0];
        float2 w0 = make_float2(mf0.x + racc[g8][0] * inv0,
                                mf0.y + racc[g8][1] * inv0);
        *(float2*)&out[o0] = w0;
        size_t o1 = o0 + (size_t)8 * DD;
        float2 mf1 = *(const float2*)&m_feats[o1];
        float2 w1 = make_float2(mf1.x + racc[g8][2] * inv1,
                                mf1.y + racc[g8][3] * inv1);
        *(float2*)&out[o1] = w1;
    }
}

// ---------------------------------------------------------------------------
extern "C" void kernel_launch(void* const* d_in, const int* in_sizes, int n_in,
                              void* d_out, int out_size)
{
    const float* m_feats = (const float*)d_in[0];
    const int*   mask    = (const int*)d_in[1];
    const float* c_w     = (const float*)d_in[2];
    const float* c_b     = (const float*)d_in[3];
    const float* v_w     = (const float*)d_in[4];
    const float* v_b     = (const float*)d_in[5];
    float* out = (float*)d_out;

    convA_kernel<<<BB*SS*DD/4/256, 256>>>(m_feats);
    convW_kernel<<<NN*DD/4/256, 256>>>(c_w, v_w);

    cudaFuncSetAttribute(gemm_kernel,
                         cudaFuncAttributeMaxDynamicSharedMemorySize, GEMM_SMEM_B);
    dim3 gG(NN / 128, BB * SS / 128);
    gemm_kernel<<<gG, 256, GEMM_SMEM_B>>>(c_b, v_b);

    cudaFuncSetAttribute(attn_kernel,
                         cudaFuncAttributeMaxDynamicSharedMemorySize, ATTN_SMEM);
    dim3 gB(SS / 32, HH, BB);
    attn_kernel<<<gB, 256, ATTN_SMEM>>>(m_feats, mask, out);
}

// round 6
// speedup vs baseline: 3.3298x; 1.2926x over previous
#include <cuda_runtime.h>
#include <cuda_bf16.h>
#include <cstdint>

#define BB 8
#define SS 1024
#define DD 1024
#define HH 8
#define DH 128
#define NN 3072
#define SCALE 0.08838834764831845f   // 1/sqrt(128)

// ---------------------------------------------------------------------------
// Device scratch
// ---------------------------------------------------------------------------
__device__ __nv_bfloat16 g_kh[BB*HH*SS*DH];   // K hi  [bh][s][d]
__device__ __nv_bfloat16 g_kl[BB*HH*SS*DH];   // K lo
__device__ __nv_bfloat16 g_qh[BB*HH*SS*DH];   // Q hi  [bh][s][d]
__device__ __nv_bfloat16 g_ql[BB*HH*SS*DH];   // Q lo
__device__ __nv_bfloat16 g_vth[BB*HH*DH*SS];  // V^T hi [bh][d][s]
__device__ __nv_bfloat16 g_Ah[BB*SS*DD];
__device__ __nv_bfloat16 g_Al[BB*SS*DD];
__device__ __nv_bfloat16 g_Wh[NN*DD];
__device__ __nv_bfloat16 g_Wl[NN*DD];

// ---------------------------------------------------------------------------
// Split conversion
// ---------------------------------------------------------------------------
__device__ __forceinline__ void split4(float4 v, __nv_bfloat162* hi2, __nv_bfloat162* lo2) {
    __nv_bfloat16 hx = __float2bfloat16_rn(v.x);
    __nv_bfloat16 hy = __float2bfloat16_rn(v.y);
    __nv_bfloat16 hz = __float2bfloat16_rn(v.z);
    __nv_bfloat16 hw = __float2bfloat16_rn(v.w);
    hi2[0] = __nv_bfloat162(hx, hy);
    hi2[1] = __nv_bfloat162(hz, hw);
    lo2[0] = __nv_bfloat162(__float2bfloat16_rn(v.x - __bfloat162float(hx)),
                            __float2bfloat16_rn(v.y - __bfloat162float(hy)));
    lo2[1] = __nv_bfloat162(__float2bfloat16_rn(v.z - __bfloat162float(hz)),
                            __float2bfloat16_rn(v.w - __bfloat162float(hw)));
}

__global__ __launch_bounds__(256) void convA_kernel(const float* __restrict__ A) {
    int i4 = blockIdx.x * 256 + threadIdx.x;
    if (i4 >= BB*SS*DD/4) return;
    float4 v = ((const float4*)A)[i4];
    __nv_bfloat162 h[2], l[2];
    split4(v, h, l);
    ((__nv_bfloat162*)g_Ah)[i4*2]   = h[0];
    ((__nv_bfloat162*)g_Ah)[i4*2+1] = h[1];
    ((__nv_bfloat162*)g_Al)[i4*2]   = l[0];
    ((__nv_bfloat162*)g_Al)[i4*2+1] = l[1];
}

__global__ __launch_bounds__(256) void convW_kernel(const float* __restrict__ c_w,
                                                    const float* __restrict__ v_w) {
    int i4 = blockIdx.x * 256 + threadIdx.x;
    if (i4 >= NN*DD/4) return;
    int e = i4 * 4;
    int n = e >> 10, k = e & 1023;
    const float* src = (n < DD) ? (v_w + (size_t)n * DD + k)
                                : (c_w + (size_t)(n - DD) * DD + k);
    float4 v = *(const float4*)src;
    __nv_bfloat162 h[2], l[2];
    split4(v, h, l);
    ((__nv_bfloat162*)g_Wh)[i4*2]   = h[0];
    ((__nv_bfloat162*)g_Wh)[i4*2+1] = h[1];
    ((__nv_bfloat162*)g_Wl)[i4*2]   = l[0];
    ((__nv_bfloat162*)g_Wl)[i4*2+1] = l[1];
}

// ---------------------------------------------------------------------------
// mma.sync / cp.async helpers
// ---------------------------------------------------------------------------
__device__ __forceinline__ uint32_t smem_u32(const void* p) {
    uint32_t a;
    asm("{ .reg .u64 t; cvta.to.shared.u64 t, %1; cvt.u32.u64 %0, t; }" : "=r"(a) : "l"(p));
    return a;
}

__device__ __forceinline__ void ldsm_x4(uint32_t* r, uint32_t addr) {
    asm volatile("ldmatrix.sync.aligned.m8n8.x4.shared.b16 {%0,%1,%2,%3}, [%4];"
                 : "=r"(r[0]), "=r"(r[1]), "=r"(r[2]), "=r"(r[3]) : "r"(addr));
}

__device__ __forceinline__ void mma_bf16(float* c, const uint32_t* a, uint32_t b0, uint32_t b1) {
    asm volatile(
        "mma.sync.aligned.m16n8k16.row.col.f32.bf16.bf16.f32 "
        "{%0,%1,%2,%3}, {%4,%5,%6,%7}, {%8,%9}, {%0,%1,%2,%3};"
        : "+f"(c[0]), "+f"(c[1]), "+f"(c[2]), "+f"(c[3])
        : "r"(a[0]), "r"(a[1]), "r"(a[2]), "r"(a[3]), "r"(b0), "r"(b1));
}

__device__ __forceinline__ void cpa16(uint32_t dst, const void* src) {
    asm volatile("cp.async.ca.shared.global [%0], [%1], 16;" :: "r"(dst), "l"(src));
}
#define CP_COMMIT() asm volatile("cp.async.commit_group;")
#define CP_WAIT(n)  asm volatile("cp.async.wait_group %0;" :: "n"(n))

__device__ __forceinline__ void store_hilo(__nv_bfloat16* bh_, __nv_bfloat16* bl_,
                                           size_t off, float x0, float x1) {
    __nv_bfloat16 h0 = __float2bfloat16_rn(x0), h1 = __float2bfloat16_rn(x1);
    *(__nv_bfloat162*)(bh_ + off) = __nv_bfloat162(h0, h1);
    *(__nv_bfloat162*)(bl_ + off) =
        __nv_bfloat162(__float2bfloat16_rn(x0 - __bfloat162float(h0)),
                       __float2bfloat16_rn(x1 - __bfloat162float(h1)));
}

// ---------------------------------------------------------------------------
// Projection GEMM (split-bf16 HMMA, cp.async double-buffer, occ 2)
// ---------------------------------------------------------------------------
#define KC 32
#define ROWP 40
#define BUF_E (128*ROWP)
#define OFF_AH 0
#define OFF_AL (2*BUF_E)
#define OFF_BH (4*BUF_E)
#define OFF_BL (6*BUF_E)
#define GEMM_SMEM_B (8*BUF_E*2 + 512)

__device__ __forceinline__ void issue_op(uint32_t sdst, const __nv_bfloat16* g,
                                         int tid, int k0) {
#pragma unroll
    for (int j = 0; j < 2; j++) {
        int u = tid + j * 256;
        int row = u >> 2, seg = u & 3;
        cpa16(sdst + (uint32_t)(row * ROWP + seg * 8) * 2,
              g + (size_t)row * DD + k0 + seg * 8);
    }
}

__global__ __launch_bounds__(256, 2) void gemm_kernel(const float* __restrict__ c_b,
                                                      const float* __restrict__ v_b) {
    extern __shared__ __nv_bfloat16 sm[];
    float* sBias = (float*)(sm + 8 * BUF_E);
    const uint32_t sbase = smem_u32(sm);

    const int tid  = threadIdx.x;
    const int lane = tid & 31;
    const int wid  = tid >> 5;
    const int wm   = wid >> 1;
    const int wn   = wid & 1;
    const int n0   = blockIdx.x * 128;
    const int m0   = blockIdx.y * 128;

    const __nv_bfloat16* Ah = g_Ah + (size_t)m0 * DD;
    const __nv_bfloat16* Al = g_Al + (size_t)m0 * DD;
    const __nv_bfloat16* Bh = g_Wh + (size_t)n0 * DD;
    const __nv_bfloat16* Bl = g_Wl + (size_t)n0 * DD;

    const float* bp = (n0 < DD) ? (v_b + n0) : (c_b + (n0 - DD));
    if (tid < 128) sBias[tid] = bp[tid];

    float acc[2][8][4];
#pragma unroll
    for (int i = 0; i < 2; i++)
#pragma unroll
        for (int j = 0; j < 8; j++)
#pragma unroll
            for (int c = 0; c < 4; c++) acc[i][j][c] = 0.f;

    const int lrow_a = wm * 32 + (lane & 15);
    const int lrow_b0 = wn * 64 + (lane & 15);
    const int lk = ((lane >> 4) & 1) * 8;

    // prologue: chunk 0 -> buffer 0
    {
        uint32_t b0u = sbase;
        issue_op(b0u + OFF_AH * 2, Ah, tid, 0);
        issue_op(b0u + OFF_AL * 2, Al, tid, 0);
        issue_op(b0u + OFF_BH * 2, Bh, tid, 0);
        issue_op(b0u + OFF_BL * 2, Bl, tid, 0);
        CP_COMMIT();
    }

#pragma unroll 1
    for (int c = 0; c < DD / KC; c++) {
        const int cur = c & 1;
        if (c + 1 < DD / KC) {
            uint32_t bu = sbase + (uint32_t)((cur ^ 1) * BUF_E) * 2;
            int k0 = (c + 1) * KC;
            issue_op(bu + OFF_AH * 2, Ah, tid, k0);
            issue_op(bu + OFF_AL * 2, Al, tid, k0);
            issue_op(bu + OFF_BH * 2, Bh, tid, k0);
            issue_op(bu + OFF_BL * 2, Bl, tid, k0);
            CP_COMMIT();
            CP_WAIT(1);
        } else {
            CP_WAIT(0);
        }
        __syncthreads();

        const __nv_bfloat16* base = sm + cur * BUF_E;
#pragma unroll
        for (int kk = 0; kk < 2; kk++) {
            const int ke = kk * 16 + lk;
            uint32_t ah[2][4], al[2][4], bh[4][4], bl[4][4];
#pragma unroll
            for (int mi = 0; mi < 2; mi++) {
                uint32_t ad = smem_u32(base + OFF_AH + (lrow_a + mi * 16) * ROWP + ke);
                ldsm_x4(ah[mi], ad);
                ldsm_x4(al[mi], ad + (OFF_AL - OFF_AH) * 2);
            }
#pragma unroll
            for (int nb = 0; nb < 4; nb++) {
                uint32_t bd = smem_u32(base + OFF_BH + (lrow_b0 + nb * 16) * ROWP + ke);
                ldsm_x4(bh[nb], bd);
                ldsm_x4(bl[nb], bd + (OFF_BL - OFF_BH) * 2);
            }
#pragma unroll
            for (int mi = 0; mi < 2; mi++)
#pragma unroll
                for (int nb = 0; nb < 4; nb++) {
                    mma_bf16(acc[mi][nb*2+0], ah[mi], bh[nb][0], bh[nb][2]);
                    mma_bf16(acc[mi][nb*2+1], ah[mi], bh[nb][1], bh[nb][3]);
                    mma_bf16(acc[mi][nb*2+0], ah[mi], bl[nb][0], bl[nb][2]);
                    mma_bf16(acc[mi][nb*2+1], ah[mi], bl[nb][1], bl[nb][3]);
                    mma_bf16(acc[mi][nb*2+0], al[mi], bh[nb][0], bh[nb][2]);
                    mma_bf16(acc[mi][nb*2+1], al[mi], bh[nb][1], bh[nb][3]);
                }
        }
        __syncthreads();
    }

    // epilogue -> bf16 scratch
    const int kind = n0 >> 10;
    const int h = (n0 >> 7) & 7;
    const int b_ = m0 >> 10;
    const int g = lane >> 2;
    const int tc = (lane & 3) * 2;
    const size_t bh_off = (size_t)(b_ * HH + h);

#pragma unroll
    for (int mi = 0; mi < 2; mi++) {
#pragma unroll
        for (int nj = 0; nj < 8; nj++) {
            const float* a4 = acc[mi][nj];
            int d = wn * 64 + nj * 8 + tc;
            float bx = sBias[d], by = sBias[d + 1];
            int s0 = (m0 + wm * 32 + mi * 16 + g) & 1023;
            float x0 = a4[0] + bx, x1 = a4[1] + by;
            float x2 = a4[2] + bx, x3 = a4[3] + by;
            if (kind == 2) {
                __nv_bfloat16* dst = g_vth + bh_off * DH * SS;
                dst[(size_t)d * SS + s0]           = __float2bfloat16_rn(x0);
                dst[(size_t)(d + 1) * SS + s0]     = __float2bfloat16_rn(x1);
                dst[(size_t)d * SS + s0 + 8]       = __float2bfloat16_rn(x2);
                dst[(size_t)(d + 1) * SS + s0 + 8] = __float2bfloat16_rn(x3);
            } else {
                __nv_bfloat16* dh_ = (kind == 0) ? g_kh : g_qh;
                __nv_bfloat16* dl_ = (kind == 0) ? g_kl : g_ql;
                size_t base_off = (bh_off * SS + s0) * DH + d;
                store_hilo(dh_, dl_, base_off, x0, x1);
                store_hilo(dh_, dl_, base_off + 8 * DH, x2, x3);
            }
        }
    }
}

// ---------------------------------------------------------------------------
// Attention: scores -> global (w region), softmax in regs, PV HMMA.  occ 2.
// ---------------------------------------------------------------------------
#define KP 136                       // K/Q tile pitch (bf16)
#define PHP 1032                     // Ph pitch (bf16)
#define VP 72                        // V tile pitch (bf16)

#define SOFF_KH   0
#define SOFF_KL   8704
#define SOFF_U    17408              // union: phase1 Q (hi/lo) | phase3 Ph+V
#define SOFF_QH   SOFF_U
#define SOFF_QL   (SOFF_U + 34816)
#define SOFF_PH   SOFF_U
#define SOFF_V    (SOFF_U + 66048)   // 83456
#define SOFF_MASK (SOFF_U + 84480)   // 101888
#define ATTN_SMEM (SOFF_MASK + 4096) // 105984 bytes

__global__ __launch_bounds__(256, 2) void attn_kernel(
    const float* __restrict__ m_feats,
    const int*   __restrict__ mask,
    float* __restrict__ out)
{
    extern __shared__ char smc[];
    __nv_bfloat16* sKh   = (__nv_bfloat16*)(smc + SOFF_KH);
    __nv_bfloat16* sKl   = (__nv_bfloat16*)(smc + SOFF_KL);
    __nv_bfloat16* sQh   = (__nv_bfloat16*)(smc + SOFF_QH);
    __nv_bfloat16* sQl   = (__nv_bfloat16*)(smc + SOFF_QL);
    __nv_bfloat16* sPh   = (__nv_bfloat16*)(smc + SOFF_PH);
    __nv_bfloat16* sV    = (__nv_bfloat16*)(smc + SOFF_V);
    int*           sMask = (int*)(smc + SOFF_MASK);

    const int tid  = threadIdx.x;
    const int lane = tid & 31;
    const int wid  = tid >> 5;
    const int b  = blockIdx.z;
    const int h  = blockIdx.y;
    const int i0 = blockIdx.x * 32;
    const size_t bh = (size_t)(b * HH + h);
    const size_t wbase = (size_t)BB * SS * DD + (bh * SS + i0) * SS;

    for (int j = tid; j < SS; j += 256) sMask[j] = mask[b * SS + j];
#pragma unroll
    for (int it = 0; it < 2; it++) {
        int p = tid + it * 256;
        int row = p >> 4, seg = p & 15;
        size_t go = (bh * SS + i0 + row) * DH + seg * 8;
        *(uint4*)(sKh + row * KP + seg * 8) = *(const uint4*)(g_kh + go);
        *(uint4*)(sKl + row * KP + seg * 8) = *(const uint4*)(g_kl + go);
    }
    __syncthreads();

    const int wm = wid >> 2;
    const int wn = wid & 3;
    const int lr16 = lane & 15;
    const int lkb = (lane >> 4) * 8;
    const int grow = lane >> 2;
    const int gcol = (lane & 3) * 2;

    // ================= Phase 1: scores -> global (raw, masked, scaled) ======
#pragma unroll 1
    for (int ct = 0; ct < 8; ct++) {
#pragma unroll
        for (int it = 0; it < 8; it++) {
            int p = tid + it * 256;
            int row = p >> 4, seg = p & 15;
            size_t go = (bh * SS + ct * 128 + row) * DH + seg * 8;
            *(uint4*)(sQh + row * KP + seg * 8) = *(const uint4*)(g_qh + go);
            *(uint4*)(sQl + row * KP + seg * 8) = *(const uint4*)(g_ql + go);
        }
        __syncthreads();

        float acc[4][4];
#pragma unroll
        for (int i = 0; i < 4; i++)
#pragma unroll
            for (int j = 0; j < 4; j++) acc[i][j] = 0.f;

#pragma unroll
        for (int ks = 0; ks < 8; ks++) {
            const int ke = ks * 16 + lkb;
            uint32_t kh[4], kl[4], qh[2][4], ql[2][4];
            uint32_t ad = smem_u32(sKh + (wm * 16 + lr16) * KP + ke);
            ldsm_x4(kh, ad);
            ldsm_x4(kl, ad + (SOFF_KL - SOFF_KH));
#pragma unroll
            for (int nb = 0; nb < 2; nb++) {
                uint32_t bd = smem_u32(sQh + (wn * 32 + nb * 16 + lr16) * KP + ke);
                ldsm_x4(qh[nb], bd);
                ldsm_x4(ql[nb], bd + (SOFF_QL - SOFF_QH));
            }
#pragma unroll
            for (int nb = 0; nb < 2; nb++) {
                mma_bf16(acc[nb*2+0], kh, qh[nb][0], qh[nb][2]);
                mma_bf16(acc[nb*2+1], kh, qh[nb][1], qh[nb][3]);
                mma_bf16(acc[nb*2+0], kh, ql[nb][0], ql[nb][2]);
                mma_bf16(acc[nb*2+1], kh, ql[nb][1], ql[nb][3]);
                mma_bf16(acc[nb*2+0], kl, qh[nb][0], qh[nb][2]);
                mma_bf16(acc[nb*2+1], kl, qh[nb][1], qh[nb][3]);
            }
        }

#pragma unroll
        for (int g8 = 0; g8 < 4; g8++) {
            int jg = ct * 128 + wn * 32 + g8 * 8 + gcol;
            bool m0 = sMask[jg] != 0, m1 = sMask[jg + 1] != 0;
            int ir = wm * 16 + grow;
            float2 r0, r1;
            r0.x = m0 ? acc[g8][0] * SCALE : -1e9f;
            r0.y = m1 ? acc[g8][1] * SCALE : -1e9f;
            r1.x = m0 ? acc[g8][2] * SCALE : -1e9f;
            r1.y = m1 ? acc[g8][3] * SCALE : -1e9f;
            *(float2*)&out[wbase + (size_t)ir * SS + jg]       = r0;
            *(float2*)&out[wbase + (size_t)(ir + 8) * SS + jg] = r1;
        }
        __syncthreads();
    }

    // ================= Phase 2: softmax (row in regs) -> w + Ph =============
    {
#pragma unroll 1
        for (int r = 0; r < 4; r++) {
            int i = wid * 4 + r;
            float* rowp = out + wbase + (size_t)i * SS;
            float2 ev[16];
#pragma unroll
            for (int k = 0; k < 16; k++)
                ev[k] = *(const float2*)&rowp[lane * 2 + k * 64];
            float mx = -3.0e38f;
#pragma unroll
            for (int k = 0; k < 16; k++)
                mx = fmaxf(mx, fmaxf(ev[k].x, ev[k].y));
#pragma unroll
            for (int o = 16; o; o >>= 1) mx = fmaxf(mx, __shfl_xor_sync(~0u, mx, o));
            float sum = 0.f;
#pragma unroll
            for (int k = 0; k < 16; k++) {
                ev[k].x = __expf(ev[k].x - mx);
                ev[k].y = __expf(ev[k].y - mx);
                sum += ev[k].x + ev[k].y;
            }
#pragma unroll
            for (int o = 16; o; o >>= 1) sum += __shfl_xor_sync(~0u, sum, o);
            float inv = 1.0f / sum;
            __nv_bfloat162* prow = (__nv_bfloat162*)(sPh + (size_t)i * PHP);
#pragma unroll
            for (int k = 0; k < 16; k++) {
                float w0 = ev[k].x * inv, w1 = ev[k].y * inv;
                *(float2*)&rowp[lane * 2 + k * 64] = make_float2(w0, w1);
                prow[lane + k * 32] =
                    __nv_bfloat162(__float2bfloat16_rn(w0), __float2bfloat16_rn(w1));
            }
        }
    }
    __syncthreads();

    // ================= Phase 3: R = P @ V^T-tiles ===========================
    float racc[4][4];
#pragma unroll
    for (int i = 0; i < 4; i++)
#pragma unroll
        for (int j = 0; j < 4; j++) racc[i][j] = 0.f;

#pragma unroll 1
    for (int jc = 0; jc < 16; jc++) {
#pragma unroll
        for (int it = 0; it < 4; it++) {
            int p = tid + it * 256;
            int row = p >> 3, seg = p & 7;
            *(uint4*)(sV + row * VP + seg * 8) =
                *(const uint4*)(g_vth + (bh * DH + row) * SS + jc * 64 + seg * 8);
        }
        __syncthreads();

#pragma unroll
        for (int ks = 0; ks < 4; ks++) {
            uint32_t pa[4], vh[2][4];
            ldsm_x4(pa, smem_u32(sPh + (size_t)(wm * 16 + lr16) * PHP
                                 + jc * 64 + ks * 16 + lkb));
#pragma unroll
            for (int nb = 0; nb < 2; nb++)
                ldsm_x4(vh[nb], smem_u32(sV + (wn * 32 + nb * 16 + lr16) * VP
                                         + ks * 16 + lkb));
#pragma unroll
            for (int nb = 0; nb < 2; nb++) {
                mma_bf16(racc[nb*2+0], pa, vh[nb][0], vh[nb][2]);
                mma_bf16(racc[nb*2+1], pa, vh[nb][1], vh[nb][3]);
            }
        }
        __syncthreads();
    }

    // ---- epilogue: out = m_feats + R (P already normalized) ----
#pragma unroll
    for (int g8 = 0; g8 < 4; g8++) {
        int d = wn * 32 + g8 * 8 + gcol;
        int ir = wm * 16 + grow;
        size_t o0 = ((size_t)b * SS + i0 + ir) * DD + h * DH + d;
        float2 mf0 = *(const float2*)&m_feats[o0];
        *(float2*)&out[o0] = make_float2(mf0.x + racc[g8][0], mf0.y + racc[g8][1]);
        size_t o1 = o0 + (size_t)8 * DD;
        float2 mf1 = *(const float2*)&m_feats[o1];
        *(float2*)&out[o1] = make_float2(mf1.x + racc[g8][2], mf1.y + racc[g8][3]);
    }
}

// ---------------------------------------------------------------------------
extern "C" void kernel_launch(void* const* d_in, const int* in_sizes, int n_in,
                              void* d_out, int out_size)
{
    const float* m_feats = (const float*)d_in[0];
    const int*   mask    = (const int*)d_in[1];
    const float* c_w     = (const float*)d_in[2];
    const float* c_b     = (const float*)d_in[3];
    const float* v_w     = (const float*)d_in[4];
    const float* v_b     = (const float*)d_in[5];
    float* out = (float*)d_out;

    convA_kernel<<<BB*SS*DD/4/256, 256>>>(m_feats);
    convW_kernel<<<NN*DD/4/256, 256>>>(c_w, v_w);

    cudaFuncSetAttribute(gemm_kernel,
                         cudaFuncAttributeMaxDynamicSharedMemorySize, GEMM_SMEM_B);
    dim3 gG(NN / 128, BB * SS / 128);
    gemm_kernel<<<gG, 256, GEMM_SMEM_B>>>(c_b, v_b);

    cudaFuncSetAttribute(attn_kernel,
                         cudaFuncAttributeMaxDynamicSharedMemorySize, ATTN_SMEM);
    dim3 gB(SS / 32, HH, BB);
    attn_kernel<<<gB, 256, ATTN_SMEM>>>(m_feats, mask, out);
}

// round 7
// speedup vs baseline: 3.6244x; 1.0885x over previous
#include <cuda_runtime.h>
#include <cuda_bf16.h>
#include <cstdint>

#define BB 8
#define SS 1024
#define DD 1024
#define HH 8
#define DH 128
#define NN 3072
#define SCALE 0.08838834764831845f   // 1/sqrt(128)

// ---------------------------------------------------------------------------
// Device scratch
// ---------------------------------------------------------------------------
__device__ __nv_bfloat16 g_kh[BB*HH*SS*DH];   // K hi  [bh][s][d]
__device__ __nv_bfloat16 g_kl[BB*HH*SS*DH];   // K lo
__device__ __nv_bfloat16 g_qh[BB*HH*SS*DH];   // Q hi  [bh][s][d]
__device__ __nv_bfloat16 g_ql[BB*HH*SS*DH];   // Q lo
__device__ __nv_bfloat16 g_vth[BB*HH*DH*SS];  // V^T hi [bh][d][s]
__device__ __nv_bfloat16 g_ph[(size_t)BB*HH*SS*SS]; // normalized P bf16 [bh][i][j]
__device__ __nv_bfloat16 g_Ah[BB*SS*DD];
__device__ __nv_bfloat16 g_Al[BB*SS*DD];
__device__ __nv_bfloat16 g_Wh[NN*DD];
__device__ __nv_bfloat16 g_Wl[NN*DD];

// ---------------------------------------------------------------------------
// Split conversion
// ---------------------------------------------------------------------------
__device__ __forceinline__ void split4(float4 v, __nv_bfloat162* hi2, __nv_bfloat162* lo2) {
    __nv_bfloat16 hx = __float2bfloat16_rn(v.x);
    __nv_bfloat16 hy = __float2bfloat16_rn(v.y);
    __nv_bfloat16 hz = __float2bfloat16_rn(v.z);
    __nv_bfloat16 hw = __float2bfloat16_rn(v.w);
    hi2[0] = __nv_bfloat162(hx, hy);
    hi2[1] = __nv_bfloat162(hz, hw);
    lo2[0] = __nv_bfloat162(__float2bfloat16_rn(v.x - __bfloat162float(hx)),
                            __float2bfloat16_rn(v.y - __bfloat162float(hy)));
    lo2[1] = __nv_bfloat162(__float2bfloat16_rn(v.z - __bfloat162float(hz)),
                            __float2bfloat16_rn(v.w - __bfloat162float(hw)));
}

__global__ __launch_bounds__(256) void convA_kernel(const float* __restrict__ A) {
    int i4 = blockIdx.x * 256 + threadIdx.x;
    if (i4 >= BB*SS*DD/4) return;
    float4 v = ((const float4*)A)[i4];
    __nv_bfloat162 h[2], l[2];
    split4(v, h, l);
    ((__nv_bfloat162*)g_Ah)[i4*2]   = h[0];
    ((__nv_bfloat162*)g_Ah)[i4*2+1] = h[1];
    ((__nv_bfloat162*)g_Al)[i4*2]   = l[0];
    ((__nv_bfloat162*)g_Al)[i4*2+1] = l[1];
}

__global__ __launch_bounds__(256) void convW_kernel(const float* __restrict__ c_w,
                                                    const float* __restrict__ v_w) {
    int i4 = blockIdx.x * 256 + threadIdx.x;
    if (i4 >= NN*DD/4) return;
    int e = i4 * 4;
    int n = e >> 10, k = e & 1023;
    const float* src = (n < DD) ? (v_w + (size_t)n * DD + k)
                                : (c_w + (size_t)(n - DD) * DD + k);
    float4 v = *(const float4*)src;
    __nv_bfloat162 h[2], l[2];
    split4(v, h, l);
    ((__nv_bfloat162*)g_Wh)[i4*2]   = h[0];
    ((__nv_bfloat162*)g_Wh)[i4*2+1] = h[1];
    ((__nv_bfloat162*)g_Wl)[i4*2]   = l[0];
    ((__nv_bfloat162*)g_Wl)[i4*2+1] = l[1];
}

// ---------------------------------------------------------------------------
// helpers
// ---------------------------------------------------------------------------
__device__ __forceinline__ uint32_t smem_u32(const void* p) {
    uint32_t a;
    asm("{ .reg .u64 t; cvta.to.shared.u64 t, %1; cvt.u32.u64 %0, t; }" : "=r"(a) : "l"(p));
    return a;
}
__device__ __forceinline__ void ldsm_x4(uint32_t* r, uint32_t addr) {
    asm volatile("ldmatrix.sync.aligned.m8n8.x4.shared.b16 {%0,%1,%2,%3}, [%4];"
                 : "=r"(r[0]), "=r"(r[1]), "=r"(r[2]), "=r"(r[3]) : "r"(addr));
}
__device__ __forceinline__ void mma_bf16(float* c, const uint32_t* a, uint32_t b0, uint32_t b1) {
    asm volatile(
        "mma.sync.aligned.m16n8k16.row.col.f32.bf16.bf16.f32 "
        "{%0,%1,%2,%3}, {%4,%5,%6,%7}, {%8,%9}, {%0,%1,%2,%3};"
        : "+f"(c[0]), "+f"(c[1]), "+f"(c[2]), "+f"(c[3])
        : "r"(a[0]), "r"(a[1]), "r"(a[2]), "r"(a[3]), "r"(b0), "r"(b1));
}
__device__ __forceinline__ void cpa16(uint32_t dst, const void* src) {
    asm volatile("cp.async.cg.shared.global [%0], [%1], 16;" :: "r"(dst), "l"(src));
}
#define CP_COMMIT() asm volatile("cp.async.commit_group;")
#define CP_WAIT(n)  asm volatile("cp.async.wait_group %0;" :: "n"(n))

__device__ __forceinline__ void store_hilo(__nv_bfloat16* bh_, __nv_bfloat16* bl_,
                                           size_t off, float x0, float x1) {
    __nv_bfloat16 h0 = __float2bfloat16_rn(x0), h1 = __float2bfloat16_rn(x1);
    *(__nv_bfloat162*)(bh_ + off) = __nv_bfloat162(h0, h1);
    *(__nv_bfloat162*)(bl_ + off) =
        __nv_bfloat162(__float2bfloat16_rn(x0 - __bfloat162float(h0)),
                       __float2bfloat16_rn(x1 - __bfloat162float(h1)));
}

// ---------------------------------------------------------------------------
// Projection GEMM (split-bf16 HMMA, cp.async.cg double-buffer, occ 2)
// ---------------------------------------------------------------------------
#define KC 32
#define ROWP 40
#define BUF_E (128*ROWP)
#define OFF_AH 0
#define OFF_AL (2*BUF_E)
#define OFF_BH (4*BUF_E)
#define OFF_BL (6*BUF_E)
#define GEMM_SMEM_B (8*BUF_E*2 + 512)

__device__ __forceinline__ void issue_op(uint32_t sdst, const __nv_bfloat16* g,
                                         int tid, int k0) {
#pragma unroll
    for (int j = 0; j < 2; j++) {
        int u = tid + j * 256;
        int row = u >> 2, seg = u & 3;
        cpa16(sdst + (uint32_t)(row * ROWP + seg * 8) * 2,
              g + (size_t)row * DD + k0 + seg * 8);
    }
}

__global__ __launch_bounds__(256, 2) void gemm_kernel(const float* __restrict__ c_b,
                                                      const float* __restrict__ v_b) {
    extern __shared__ __nv_bfloat16 sm[];
    float* sBias = (float*)(sm + 8 * BUF_E);
    const uint32_t sbase = smem_u32(sm);

    const int tid  = threadIdx.x;
    const int lane = tid & 31;
    const int wid  = tid >> 5;
    const int wm   = wid >> 1;
    const int wn   = wid & 1;
    const int n0   = blockIdx.x * 128;
    const int m0   = blockIdx.y * 128;

    const __nv_bfloat16* Ah = g_Ah + (size_t)m0 * DD;
    const __nv_bfloat16* Al = g_Al + (size_t)m0 * DD;
    const __nv_bfloat16* Bh = g_Wh + (size_t)n0 * DD;
    const __nv_bfloat16* Bl = g_Wl + (size_t)n0 * DD;

    const float* bp = (n0 < DD) ? (v_b + n0) : (c_b + (n0 - DD));
    if (tid < 128) sBias[tid] = bp[tid];

    float acc[2][8][4];
#pragma unroll
    for (int i = 0; i < 2; i++)
#pragma unroll
        for (int j = 0; j < 8; j++)
#pragma unroll
            for (int c = 0; c < 4; c++) acc[i][j][c] = 0.f;

    const int lrow_a = wm * 32 + (lane & 15);
    const int lrow_b0 = wn * 64 + (lane & 15);
    const int lk = ((lane >> 4) & 1) * 8;

    {
        issue_op(sbase + OFF_AH * 2, Ah, tid, 0);
        issue_op(sbase + OFF_AL * 2, Al, tid, 0);
        issue_op(sbase + OFF_BH * 2, Bh, tid, 0);
        issue_op(sbase + OFF_BL * 2, Bl, tid, 0);
        CP_COMMIT();
    }

#pragma unroll 1
    for (int c = 0; c < DD / KC; c++) {
        const int cur = c & 1;
        if (c + 1 < DD / KC) {
            uint32_t bu = sbase + (uint32_t)((cur ^ 1) * BUF_E) * 2;
            int k0 = (c + 1) * KC;
            issue_op(bu + OFF_AH * 2, Ah, tid, k0);
            issue_op(bu + OFF_AL * 2, Al, tid, k0);
            issue_op(bu + OFF_BH * 2, Bh, tid, k0);
            issue_op(bu + OFF_BL * 2, Bl, tid, k0);
            CP_COMMIT();
            CP_WAIT(1);
        } else {
            CP_WAIT(0);
        }
        __syncthreads();

        const __nv_bfloat16* base = sm + cur * BUF_E;
#pragma unroll
        for (int kk = 0; kk < 2; kk++) {
            const int ke = kk * 16 + lk;
            uint32_t ah[2][4], al[2][4], bh[4][4], bl[4][4];
#pragma unroll
            for (int mi = 0; mi < 2; mi++) {
                uint32_t ad = smem_u32(base + OFF_AH + (lrow_a + mi * 16) * ROWP + ke);
                ldsm_x4(ah[mi], ad);
                ldsm_x4(al[mi], ad + (OFF_AL - OFF_AH) * 2);
            }
#pragma unroll
            for (int nb = 0; nb < 4; nb++) {
                uint32_t bd = smem_u32(base + OFF_BH + (lrow_b0 + nb * 16) * ROWP + ke);
                ldsm_x4(bh[nb], bd);
                ldsm_x4(bl[nb], bd + (OFF_BL - OFF_BH) * 2);
            }
#pragma unroll
            for (int mi = 0; mi < 2; mi++)
#pragma unroll
                for (int nb = 0; nb < 4; nb++) {
                    mma_bf16(acc[mi][nb*2+0], ah[mi], bh[nb][0], bh[nb][2]);
                    mma_bf16(acc[mi][nb*2+1], ah[mi], bh[nb][1], bh[nb][3]);
                    mma_bf16(acc[mi][nb*2+0], ah[mi], bl[nb][0], bl[nb][2]);
                    mma_bf16(acc[mi][nb*2+1], ah[mi], bl[nb][1], bl[nb][3]);
                    mma_bf16(acc[mi][nb*2+0], al[mi], bh[nb][0], bh[nb][2]);
                    mma_bf16(acc[mi][nb*2+1], al[mi], bh[nb][1], bh[nb][3]);
                }
        }
        __syncthreads();
    }

    const int kind = n0 >> 10;
    const int h = (n0 >> 7) & 7;
    const int b_ = m0 >> 10;
    const int g = lane >> 2;
    const int tc = (lane & 3) * 2;
    const size_t bh_off = (size_t)(b_ * HH + h);

#pragma unroll
    for (int mi = 0; mi < 2; mi++) {
#pragma unroll
        for (int nj = 0; nj < 8; nj++) {
            const float* a4 = acc[mi][nj];
            int d = wn * 64 + nj * 8 + tc;
            float bx = sBias[d], by = sBias[d + 1];
            int s0 = (m0 + wm * 32 + mi * 16 + g) & 1023;
            float x0 = a4[0] + bx, x1 = a4[1] + by;
            float x2 = a4[2] + bx, x3 = a4[3] + by;
            if (kind == 2) {
                __nv_bfloat16* dst = g_vth + bh_off * DH * SS;
                dst[(size_t)d * SS + s0]           = __float2bfloat16_rn(x0);
                dst[(size_t)(d + 1) * SS + s0]     = __float2bfloat16_rn(x1);
                dst[(size_t)d * SS + s0 + 8]       = __float2bfloat16_rn(x2);
                dst[(size_t)(d + 1) * SS + s0 + 8] = __float2bfloat16_rn(x3);
            } else {
                __nv_bfloat16* dh_ = (kind == 0) ? g_kh : g_qh;
                __nv_bfloat16* dl_ = (kind == 0) ? g_kl : g_ql;
                size_t base_off = (bh_off * SS + s0) * DH + d;
                store_hilo(dh_, dl_, base_off, x0, x1);
                store_hilo(dh_, dl_, base_off + 8 * DH, x2, x3);
            }
        }
    }
}

// ---------------------------------------------------------------------------
// Attention, TI=64: scores->global, softmax in regs -> w + g_ph, PV HMMA.
// 8 warps as 2m x 4n; warp tile 32x32. occ 2.
// ---------------------------------------------------------------------------
#define KP 136
#define SOFF_KH   0                     // 64x136x2 = 17408
#define SOFF_KL   17408
#define SOFF_U    34816                 // Qh(34816)+Ql(34816) | Ph(17408)+V(34816)
#define SOFF_MASK 104448
#define ATTN_SMEM 108544
#define PH_BYTES  17408

__global__ __launch_bounds__(256, 2) void attn_kernel(
    const float* __restrict__ m_feats,
    const int*   __restrict__ mask,
    float* __restrict__ out)
{
    extern __shared__ char smc[];
    __nv_bfloat16* sKh = (__nv_bfloat16*)(smc + SOFF_KH);
    __nv_bfloat16* sQh = (__nv_bfloat16*)(smc + SOFF_U);
    __nv_bfloat16* sPh = (__nv_bfloat16*)(smc + SOFF_U);
    __nv_bfloat16* sV  = (__nv_bfloat16*)(smc + SOFF_U + PH_BYTES);
    int*           sMask = (int*)(smc + SOFF_MASK);
    const uint32_t uKh = smem_u32(sKh);
    const uint32_t uQh = smem_u32(sQh);
    const uint32_t uPh = uQh;
    const uint32_t uV  = uQh + PH_BYTES;

    const int tid  = threadIdx.x;
    const int lane = tid & 31;
    const int wid  = tid >> 5;
    const int b  = blockIdx.z;
    const int h  = blockIdx.y;
    const int i0 = blockIdx.x * 64;
    const size_t bh = (size_t)(b * HH + h);
    const size_t wbase = (size_t)BB * SS * DD + (bh * SS + i0) * SS;

    const int wm = wid >> 2;        // 0..1 -> rows wm*32
    const int wn = wid & 3;         // 0..3
    const int lr16 = lane & 15;
    const int lkb = (lane >> 4) * 8;
    const int grow = lane >> 2;
    const int gcol = (lane & 3) * 2;

    for (int j = tid; j < SS; j += 256) sMask[j] = mask[b * SS + j];
    // K tile fill (64 rows, hi+lo)
#pragma unroll
    for (int it = 0; it < 4; it++) {
        int p = tid + it * 256;
        int row = p >> 4, seg = p & 15;
        size_t go = (bh * SS + i0 + row) * DH + seg * 8;
        uint32_t so = (uint32_t)(row * KP + seg * 8) * 2;
        cpa16(uKh + so, g_kh + go);
        cpa16(uKh + (SOFF_KL - SOFF_KH) + so, g_kl + go);
    }
    CP_COMMIT();
    CP_WAIT(0);
    __syncthreads();

    // ================= Phase 1: scores -> global =================
#pragma unroll 1
    for (int ct = 0; ct < 8; ct++) {
#pragma unroll
        for (int it = 0; it < 8; it++) {
            int p = tid + it * 256;
            int row = p >> 4, seg = p & 15;
            size_t go = (bh * SS + ct * 128 + row) * DH + seg * 8;
            uint32_t so = (uint32_t)(row * KP + seg * 8) * 2;
            cpa16(uQh + so, g_qh + go);
            cpa16(uQh + 34816 + so, g_ql + go);
        }
        CP_COMMIT();
        CP_WAIT(0);
        __syncthreads();

        float acc[2][4][4];
#pragma unroll
        for (int i = 0; i < 2; i++)
#pragma unroll
            for (int j = 0; j < 4; j++)
#pragma unroll
                for (int cc = 0; cc < 4; cc++) acc[i][j][cc] = 0.f;

#pragma unroll
        for (int ks = 0; ks < 8; ks++) {
            const int ke = ks * 16 + lkb;
            uint32_t kh[2][4], kl[2][4], qh[2][4], ql[2][4];
#pragma unroll
            for (int mi = 0; mi < 2; mi++) {
                uint32_t ad = uKh + (uint32_t)((wm * 32 + mi * 16 + lr16) * KP + ke) * 2;
                ldsm_x4(kh[mi], ad);
                ldsm_x4(kl[mi], ad + (SOFF_KL - SOFF_KH));
            }
#pragma unroll
            for (int nb = 0; nb < 2; nb++) {
                uint32_t bd = uQh + (uint32_t)((wn * 32 + nb * 16 + lr16) * KP + ke) * 2;
                ldsm_x4(qh[nb], bd);
                ldsm_x4(ql[nb], bd + 34816);
            }
#pragma unroll
            for (int mi = 0; mi < 2; mi++)
#pragma unroll
                for (int nb = 0; nb < 2; nb++) {
                    mma_bf16(acc[mi][nb*2+0], kh[mi], qh[nb][0], qh[nb][2]);
                    mma_bf16(acc[mi][nb*2+1], kh[mi], qh[nb][1], qh[nb][3]);
                    mma_bf16(acc[mi][nb*2+0], kh[mi], ql[nb][0], ql[nb][2]);
                    mma_bf16(acc[mi][nb*2+1], kh[mi], ql[nb][1], ql[nb][3]);
                    mma_bf16(acc[mi][nb*2+0], kl[mi], qh[nb][0], qh[nb][2]);
                    mma_bf16(acc[mi][nb*2+1], kl[mi], qh[nb][1], qh[nb][3]);
                }
        }

#pragma unroll
        for (int mi = 0; mi < 2; mi++)
#pragma unroll
            for (int nj = 0; nj < 4; nj++) {
                int jg = ct * 128 + wn * 32 + (nj >> 1) * 16 + (nj & 1) * 8 + gcol;
                bool m0 = sMask[jg] != 0, m1 = sMask[jg + 1] != 0;
                int ir = wm * 32 + mi * 16 + grow;
                const float* a4 = acc[mi][nj];
                float2 r0, r1;
                r0.x = m0 ? a4[0] * SCALE : -1e9f;
                r0.y = m1 ? a4[1] * SCALE : -1e9f;
                r1.x = m0 ? a4[2] * SCALE : -1e9f;
                r1.y = m1 ? a4[3] * SCALE : -1e9f;
                *(float2*)&out[wbase + (size_t)ir * SS + jg]       = r0;
                *(float2*)&out[wbase + (size_t)(ir + 8) * SS + jg] = r1;
            }
        __syncthreads();
    }
    __threadfence_block();
    __syncthreads();

    // ================= Phase 2: softmax -> w + g_ph =================
#pragma unroll 1
    for (int r = 0; r < 8; r++) {
        int i = wid * 8 + r;
        float* rowp = out + wbase + (size_t)i * SS;
        float2 ev[16];
#pragma unroll
        for (int k = 0; k < 16; k++)
            ev[k] = *(const float2*)&rowp[lane * 2 + k * 64];
        float mx = -3.0e38f;
#pragma unroll
        for (int k = 0; k < 16; k++)
            mx = fmaxf(mx, fmaxf(ev[k].x, ev[k].y));
#pragma unroll
        for (int o = 16; o; o >>= 1) mx = fmaxf(mx, __shfl_xor_sync(~0u, mx, o));
        float sum = 0.f;
#pragma unroll
        for (int k = 0; k < 16; k++) {
            ev[k].x = __expf(ev[k].x - mx);
            ev[k].y = __expf(ev[k].y - mx);
            sum += ev[k].x + ev[k].y;
        }
#pragma unroll
        for (int o = 16; o; o >>= 1) sum += __shfl_xor_sync(~0u, sum, o);
        float inv = 1.0f / sum;
        __nv_bfloat162* prow = (__nv_bfloat162*)(g_ph + (bh * SS + i0 + i) * SS);
#pragma unroll
        for (int k = 0; k < 16; k++) {
            float w0 = ev[k].x * inv, w1 = ev[k].y * inv;
            *(float2*)&rowp[lane * 2 + k * 64] = make_float2(w0, w1);
            prow[lane + k * 32] =
                __nv_bfloat162(__float2bfloat16_rn(w0), __float2bfloat16_rn(w1));
        }
    }
    __threadfence_block();
    __syncthreads();

    // ================= Phase 3: R = P @ V =================
    float racc[2][4][4];
#pragma unroll
    for (int i = 0; i < 2; i++)
#pragma unroll
        for (int j = 0; j < 4; j++)
#pragma unroll
            for (int cc = 0; cc < 4; cc++) racc[i][j][cc] = 0.f;

#pragma unroll 1
    for (int jc = 0; jc < 8; jc++) {
        // P tile: 64 i-rows x 128 j
#pragma unroll
        for (int it = 0; it < 4; it++) {
            int p = tid + it * 256;
            int row = p >> 4, seg = p & 15;
            cpa16(uPh + (uint32_t)(row * KP + seg * 8) * 2,
                  g_ph + (bh * SS + i0 + row) * SS + jc * 128 + seg * 8);
        }
        // V tile: 128 d-rows x 128 j
#pragma unroll
        for (int it = 0; it < 8; it++) {
            int p = tid + it * 256;
            int row = p >> 4, seg = p & 15;
            cpa16(uV + (uint32_t)(row * KP + seg * 8) * 2,
                  g_vth + (bh * DH + row) * SS + jc * 128 + seg * 8);
        }
        CP_COMMIT();
        CP_WAIT(0);
        __syncthreads();

#pragma unroll
        for (int ks = 0; ks < 8; ks++) {
            const int ke = ks * 16 + lkb;
            uint32_t pa[2][4], vh[2][4];
#pragma unroll
            for (int mi = 0; mi < 2; mi++)
                ldsm_x4(pa[mi], uPh + (uint32_t)((wm * 32 + mi * 16 + lr16) * KP + ke) * 2);
#pragma unroll
            for (int nb = 0; nb < 2; nb++)
                ldsm_x4(vh[nb], uV + (uint32_t)((wn * 32 + nb * 16 + lr16) * KP + ke) * 2);
#pragma unroll
            for (int mi = 0; mi < 2; mi++)
#pragma unroll
                for (int nb = 0; nb < 2; nb++) {
                    mma_bf16(racc[mi][nb*2+0], pa[mi], vh[nb][0], vh[nb][2]);
                    mma_bf16(racc[mi][nb*2+1], pa[mi], vh[nb][1], vh[nb][3]);
                }
        }
        __syncthreads();
    }

    // ---- epilogue: out = m_feats + R ----
#pragma unroll
    for (int mi = 0; mi < 2; mi++)
#pragma unroll
        for (int nj = 0; nj < 4; nj++) {
            int d = wn * 32 + (nj >> 1) * 16 + (nj & 1) * 8 + gcol;
            int ir = wm * 32 + mi * 16 + grow;
            const float* a4 = racc[mi][nj];
            size_t o0 = ((size_t)b * SS + i0 + ir) * DD + h * DH + d;
            float2 mf0 = *(const float2*)&m_feats[o0];
            *(float2*)&out[o0] = make_float2(mf0.x + a4[0], mf0.y + a4[1]);
            size_t o1 = o0 + (size_t)8 * DD;
            float2 mf1 = *(const float2*)&m_feats[o1];
            *(float2*)&out[o1] = make_float2(mf1.x + a4[2], mf1.y + a4[3]);
        }
}

// ---------------------------------------------------------------------------
extern "C" void kernel_launch(void* const* d_in, const int* in_sizes, int n_in,
                              void* d_out, int out_size)
{
    const float* m_feats = (const float*)d_in[0];
    const int*   mask    = (const int*)d_in[1];
    const float* c_w     = (const float*)d_in[2];
    const float* c_b     = (const float*)d_in[3];
    const float* v_w     = (const float*)d_in[4];
    const float* v_b     = (const float*)d_in[5];
    float* out = (float*)d_out;

    convA_kernel<<<BB*SS*DD/4/256, 256>>>(m_feats);
    convW_kernel<<<NN*DD/4/256, 256>>>(c_w, v_w);

    cudaFuncSetAttribute(gemm_kernel,
                         cudaFuncAttributeMaxDynamicSharedMemorySize, GEMM_SMEM_B);
    dim3 gG(NN / 128, BB * SS / 128);
    gemm_kernel<<<gG, 256, GEMM_SMEM_B>>>(c_b, v_b);

    cudaFuncSetAttribute(attn_kernel,
                         cudaFuncAttributeMaxDynamicSharedMemorySize, ATTN_SMEM);
    dim3 gB(SS / 64, HH, BB);
    attn_kernel<<<gB, 256, ATTN_SMEM>>>(m_feats, mask, out);
}